// round 1
// baseline (speedup 1.0000x reference)
#include <cuda_runtime.h>
#include <cstdint>

// ---------------- problem constants ----------------
#define HW   50176          // 224*224
#define KDIM 128            // channels (reduction dim for both GEMMs)

typedef unsigned long long ull;

// scratch: qkv [4][384][50176], attended [4][128][50176]
__device__ float g_qkv[77070336];
__device__ float g_att[25690112];

// ---------------- packed f32x2 helpers ----------------
__device__ __forceinline__ ull pack_dup(float a){
    ull r; unsigned u = __float_as_uint(a);
    asm("mov.b64 %0, {%1,%1};" : "=l"(r) : "r"(u));
    return r;
}
__device__ __forceinline__ void fma2(ull& d, ull a, ull b){
    asm("fma.rn.f32x2 %0, %1, %2, %3;" : "=l"(d) : "l"(a), "l"(b), "l"(d));
}
__device__ __forceinline__ float2 unpack2(ull v){
    unsigned lo, hi;
    asm("mov.b64 {%0,%1}, %2;" : "=r"(lo), "=r"(hi) : "l"(v));
    return make_float2(__uint_as_float(lo), __uint_as_float(hi));
}

// ---------------- GEMM: Out[b][m][p] = sum_c Wt[m][c] * X[b][c][p] + bias[m] ----------------
// Wt: [Mtot x 128] row-major. X: [B][128][HW]. Out rows stride HW.
// CTA tile 128(M) x 128(N), K chunks of 32. Thread tile 8x8 via fma.rn.f32x2.
__global__ __launch_bounds__(256)
void gemm_bias_k128(const float* __restrict__ Wt,
                    const float* __restrict__ X,
                    const float* __restrict__ bias,
                    float* __restrict__ Out,
                    int Mtot)
{
    __shared__ __align__(16) float As[128][33];   // [m][k] pad 33 -> conflict-free k reads
    __shared__ __align__(16) float Bs[32][128];   // [k][n]

    const int tid = threadIdx.x;
    const int b   = blockIdx.z;
    const int m0t = blockIdx.y * 128;
    const int n0t = blockIdx.x * 128;

    const float* Xb = X  + (size_t)b * KDIM * HW + n0t;
    const float* Wb = Wt + (size_t)m0t * KDIM;
    float*       Ob = Out + ((size_t)b * Mtot + m0t) * HW + n0t;

    const int tn = tid & 15, tm = tid >> 4;
    const int n0 = tn * 8,   m0 = tm * 8;

    ull acc[8][4];
    #pragma unroll
    for (int i = 0; i < 8; i++)
        #pragma unroll
        for (int j = 0; j < 4; j++) acc[i][j] = 0ULL;

    for (int kc = 0; kc < 4; kc++){
        // stage W tile: 128 rows x 32 k  (coalesced float4 loads, scalar stores)
        #pragma unroll
        for (int r = 0; r < 4; r++){
            int fidx = tid + r * 256;          // 0..1023 float4 indices
            int o  = fidx >> 3;                // row 0..127
            int c4 = fidx & 7;                 // which float4 in 32 floats
            float4 w4 = *(const float4*)(Wb + (size_t)o * KDIM + kc * 32 + c4 * 4);
            As[o][c4*4 + 0] = w4.x;
            As[o][c4*4 + 1] = w4.y;
            As[o][c4*4 + 2] = w4.z;
            As[o][c4*4 + 3] = w4.w;
        }
        // stage X tile: 32 k x 128 n  (fully coalesced)
        #pragma unroll
        for (int r = 0; r < 4; r++){
            int fidx = tid + r * 256;
            int k  = fidx >> 5;
            int n4 = fidx & 31;
            float4 x4 = *(const float4*)(Xb + (size_t)(kc * 32 + k) * HW + n4 * 4);
            *(float4*)&Bs[k][n4 * 4] = x4;
        }
        __syncthreads();

        #pragma unroll 4
        for (int k = 0; k < 32; k++){
            ull ad[8];
            #pragma unroll
            for (int i = 0; i < 8; i++) ad[i] = pack_dup(As[m0 + i][k]);
            ulonglong2 b01 = *(const ulonglong2*)&Bs[k][n0];
            ulonglong2 b23 = *(const ulonglong2*)&Bs[k][n0 + 4];
            #pragma unroll
            for (int i = 0; i < 8; i++){
                fma2(acc[i][0], ad[i], b01.x);
                fma2(acc[i][1], ad[i], b01.y);
                fma2(acc[i][2], ad[i], b23.x);
                fma2(acc[i][3], ad[i], b23.y);
            }
        }
        __syncthreads();
    }

    #pragma unroll
    for (int i = 0; i < 8; i++){
        float bv = bias[m0t + m0 + i];
        float2 p0 = unpack2(acc[i][0]);
        float2 p1 = unpack2(acc[i][1]);
        float2 p2 = unpack2(acc[i][2]);
        float2 p3 = unpack2(acc[i][3]);
        float4 o0 = make_float4(p0.x + bv, p0.y + bv, p1.x + bv, p1.y + bv);
        float4 o1 = make_float4(p2.x + bv, p2.y + bv, p3.x + bv, p3.y + bv);
        float* row = Ob + (size_t)(m0 + i) * HW;
        *(float4*)(row + n0)     = o0;
        *(float4*)(row + n0 + 4) = o1;
    }
}

// ---------------- windowed attention ----------------
// One CTA per (window, head). qkv: [b][384][HW] (q rows 0..127, k 128..255, v 256..383).
// att: [b][128][HW].
__global__ __launch_bounds__(256)
void attn_win(const float* __restrict__ qkv, float* __restrict__ att)
{
    __shared__ __align__(16) float qs[16][52];   // q [c][l]  (scaled), reused as out [c][l]
    __shared__ __align__(16) float ks[16][52];   // k [c][m]
    __shared__ __align__(16) float vT[52][16];   // v [m][c]
    __shared__ __align__(16) float ps[52][52];   // scores [l][m]
    __shared__ __align__(16) float pT[52][52];   // probs  [m][l]

    const int tid = threadIdx.x;
    const int wi  = blockIdx.x;      // window id: b*1024 + wh*32 + ww
    const int h   = blockIdx.y;      // head
    const int b   = wi >> 10;
    const int wh  = (wi >> 5) & 31;
    const int ww  = wi & 31;
    const int prow = wh * 7, pcol = ww * 7;

    const float* qb = qkv + ((size_t)(b * 384 + h * 16)) * HW;
    const float* kb = qb + (size_t)128 * HW;
    const float* vb = qb + (size_t)256 * HW;

    // load q,k,v (49 positions x 16 channels)
    for (int idx = tid; idx < 784; idx += 256){
        int c = idx / 49;
        int p = idx - c * 49;
        int pg = (prow + p / 7) * 224 + pcol + (p % 7);
        size_t off = (size_t)c * HW + pg;
        qs[c][p] = qb[off] * 0.25f;   // scale = 1/sqrt(16)
        ks[c][p] = kb[off];
        vT[p][c] = vb[off];
    }
    __syncthreads();

    // scores[l][m] = sum_c q[c][l] * k[c][m] ; 13x13 tiles of 4x4 = 169 threads
    if (tid < 169){
        int lt = (tid / 13) * 4;
        int mt = (tid % 13) * 4;
        float acc[4][4];
        #pragma unroll
        for (int i = 0; i < 4; i++)
            #pragma unroll
            for (int j = 0; j < 4; j++) acc[i][j] = 0.f;
        #pragma unroll 4
        for (int c = 0; c < 16; c++){
            float4 q4 = *(const float4*)&qs[c][lt];
            float4 k4 = *(const float4*)&ks[c][mt];
            float qv[4] = {q4.x, q4.y, q4.z, q4.w};
            float kv[4] = {k4.x, k4.y, k4.z, k4.w};
            #pragma unroll
            for (int i = 0; i < 4; i++)
                #pragma unroll
                for (int j = 0; j < 4; j++)
                    acc[i][j] += qv[i] * kv[j];
        }
        #pragma unroll
        for (int i = 0; i < 4; i++)
            #pragma unroll
            for (int j = 0; j < 4; j++)
                ps[lt + i][mt + j] = acc[i][j];
    }
    __syncthreads();

    // softmax over m, write transposed probs pT[m][l]
    {
        int warp = tid >> 5, lane = tid & 31;
        for (int l = warp; l < 49; l += 8){
            float s0 = ps[l][lane];
            float s1 = (lane < 17) ? ps[l][lane + 32] : -3.4e38f;
            float mx = fmaxf(s0, s1);
            #pragma unroll
            for (int o = 16; o; o >>= 1) mx = fmaxf(mx, __shfl_xor_sync(0xffffffffu, mx, o));
            float e0 = __expf(s0 - mx);
            float e1 = (lane < 17) ? __expf(s1 - mx) : 0.f;
            float sm = e0 + e1;
            #pragma unroll
            for (int o = 16; o; o >>= 1) sm += __shfl_xor_sync(0xffffffffu, sm, o);
            float inv = 1.f / sm;
            pT[lane][l] = e0 * inv;
            if (lane < 17) pT[lane + 32][l] = e1 * inv;
        }
    }
    __syncthreads();

    // out[c][l] = sum_m v[c][m] * p[l][m] ; 4x13 tiles of 4x4 = 52 threads
    if (tid < 52){
        int c0 = (tid & 3) * 4;
        int l0 = (tid >> 2) * 4;
        float acc[4][4];
        #pragma unroll
        for (int i = 0; i < 4; i++)
            #pragma unroll
            for (int j = 0; j < 4; j++) acc[i][j] = 0.f;
        for (int m = 0; m < 49; m++){
            float4 v4 = *(const float4*)&vT[m][c0];
            float4 p4 = *(const float4*)&pT[m][l0];
            float vv[4] = {v4.x, v4.y, v4.z, v4.w};
            float pv[4] = {p4.x, p4.y, p4.z, p4.w};
            #pragma unroll
            for (int i = 0; i < 4; i++)
                #pragma unroll
                for (int j = 0; j < 4; j++)
                    acc[i][j] += vv[i] * pv[j];
        }
        #pragma unroll
        for (int i = 0; i < 4; i++)
            #pragma unroll
            for (int j = 0; j < 4; j++)
                qs[c0 + i][l0 + j] = acc[i][j];   // stage through smem for coalesced writeback
    }
    __syncthreads();

    float* ab = att + ((size_t)(b * 128 + h * 16)) * HW;
    for (int idx = tid; idx < 784; idx += 256){
        int c = idx / 49;
        int p = idx - c * 49;
        int pg = (prow + p / 7) * 224 + pcol + (p % 7);
        ab[(size_t)c * HW + pg] = qs[c][p];
    }
}

// ---------------- launch ----------------
extern "C" void kernel_launch(void* const* d_in, const int* in_sizes, int n_in,
                              void* d_out, int out_size)
{
    const float* x     = (const float*)d_in[0];
    const float* w_qkv = (const float*)d_in[1];
    const float* b_qkv = (const float*)d_in[2];
    const float* w_out = (const float*)d_in[3];
    const float* b_out = (const float*)d_in[4];
    float* out = (float*)d_out;

    float *qkv = nullptr, *att = nullptr;
    cudaGetSymbolAddress((void**)&qkv, g_qkv);
    cudaGetSymbolAddress((void**)&att, g_att);

    dim3 blk(256);
    // QKV GEMM: M=384, N=50176 per batch (392 tiles of 128), B=4
    gemm_bias_k128<<<dim3(392, 3, 4), blk>>>(w_qkv, x, b_qkv, qkv, 384);
    // windowed attention: 4096 windows x 8 heads
    attn_win<<<dim3(4096, 8), blk>>>(qkv, att);
    // output projection: M=128
    gemm_bias_k128<<<dim3(392, 1, 4), blk>>>(w_out, att, b_out, out, 128);
}

// round 3
// speedup vs baseline: 1.1654x; 1.1654x over previous
#include <cuda_runtime.h>
#include <cuda_bf16.h>
#include <cstdint>

// ---------------- problem constants ----------------
#define HW    50176          // 224*224
#define NTILE 392            // HW / 128
#define BLOBS 1568           // 4 * NTILE

// scratch
__device__ float         g_qkv[77070336];   // [4][384][1024 windows][49] fp32 (window-major)
__device__ __nv_bfloat16 g_xhi[25690112];   // x tiles  [4*392][128 n][128 k] bf16 hi
__device__ __nv_bfloat16 g_xlo[25690112];
__device__ __nv_bfloat16 g_ahi[25690112];   // attn-out tiles (same layout)
__device__ __nv_bfloat16 g_alo[25690112];

// ---------------- helpers ----------------
__device__ __forceinline__ uint32_t smem_u32(const void* p){
    uint32_t a;
    asm("{ .reg .u64 t; cvta.to.shared.u64 t, %1; cvt.u32.u64 %0, t; }" : "=r"(a) : "l"(p));
    return a;
}
__device__ __forceinline__ void split_bf16(float v, __nv_bfloat16& h, __nv_bfloat16& l){
    h = __float2bfloat16(v);
    l = __float2bfloat16(v - __bfloat162float(h));
}
__device__ __forceinline__ uint32_t pack_bf2(__nv_bfloat16 a, __nv_bfloat16 b){
    return (uint32_t)__bfloat16_as_ushort(a) | ((uint32_t)__bfloat16_as_ushort(b) << 16);
}

#define LDSM_X4(r0, r1, r2, r3, addr)                                                     \
    asm volatile("ldmatrix.sync.aligned.m8n8.x4.shared.b16 {%0,%1,%2,%3}, [%4];"          \
        : "=r"(r0), "=r"(r1), "=r"(r2), "=r"(r3) : "r"(addr))

#define MMA_BF16(d, a, b0, b1)                                                            \
    asm volatile("mma.sync.aligned.m16n8k16.row.col.f32.bf16.bf16.f32 "                   \
        "{%0,%1,%2,%3}, {%4,%5,%6,%7}, {%8,%9}, {%0,%1,%2,%3};"                           \
        : "+f"((d)[0]), "+f"((d)[1]), "+f"((d)[2]), "+f"((d)[3])                          \
        : "r"((a)[0]), "r"((a)[1]), "r"((a)[2]), "r"((a)[3]), "r"(b0), "r"(b1))

// =====================================================================
// x -> n-major bf16 hi/lo tiles: tile[n][k], n = pixel (within 128-tile), k = channel
// =====================================================================
#define XCONV_SMEM (128*132*4)
__global__ __launch_bounds__(256)
void xconv(const float* __restrict__ X, __nv_bfloat16* __restrict__ Hi, __nv_bfloat16* __restrict__ Lo)
{
    extern __shared__ __align__(16) float ts[];   // [128 k][132] (padded)
    const int tid = threadIdx.x;
    const int blob = blockIdx.x;
    const int b = blob / NTILE, t = blob - b * NTILE;
    const float* xp = X + (size_t)b * 128 * HW + (size_t)t * 128;
    const size_t ob = (size_t)blob << 14;

    #pragma unroll
    for (int i = 0; i < 16; i++){
        int idx = tid + i * 256;                 // 4096 float4
        int k = idx >> 5, c4 = idx & 31;
        float4 v = *(const float4*)(xp + (size_t)k * HW + c4 * 4);
        float* d = &ts[k * 132 + c4 * 4];
        d[0] = v.x; d[1] = v.y; d[2] = v.z; d[3] = v.w;
    }
    __syncthreads();

    #pragma unroll
    for (int i = 0; i < 8; i++){
        int idx = tid + i * 256;                 // 2048 (n, kchunk) units
        int n = idx >> 4, kc = idx & 15;
        uint32_t rh[4], rl[4];
        #pragma unroll
        for (int j = 0; j < 4; j++){
            float v0 = ts[(kc * 8 + 2*j    ) * 132 + n];
            float v1 = ts[(kc * 8 + 2*j + 1) * 132 + n];
            __nv_bfloat16 h0, l0, h1, l1;
            split_bf16(v0, h0, l0); split_bf16(v1, h1, l1);
            rh[j] = pack_bf2(h0, h1);
            rl[j] = pack_bf2(l0, l1);
        }
        size_t o = ob + (size_t)n * 128 + kc * 8;
        *(uint4*)(Hi + o) = make_uint4(rh[0], rh[1], rh[2], rh[3]);
        *(uint4*)(Lo + o) = make_uint4(rl[0], rl[1], rl[2], rl[3]);
    }
}

// =====================================================================
// tensor-core GEMM (mma.sync bf16 hi/lo): Out[m][n] = sum_k W[m][k]*X[k][n] + bias[m]
// CTA tile 128x128, K=128 fully staged. 8 warps, warp tile 32x64.
// remap=0: Out fp32 row-major (stride HW). remap=1: window-major qkv layout.
// =====================================================================
#define AS 136                       // padded row stride (bf16 elems)
#define OFF_AH 0
#define OFF_AL (128*AS*2)            // 34816
#define OFF_BH (2*128*AS*2)          // 69632
#define OFF_BL (3*128*AS*2)          // 104448
#define GEMM_SMEM (4*128*AS*2)       // 139264

__global__ __launch_bounds__(256)
void gemm_mma(const float* __restrict__ W,
              const __nv_bfloat16* __restrict__ Bhi,
              const __nv_bfloat16* __restrict__ Blo,
              const float* __restrict__ bias,
              float* __restrict__ Out,
              int Mtot, int remap)
{
    extern __shared__ __align__(16) char sm[];
    const int tid  = threadIdx.x;
    const int wid  = tid >> 5;
    const int lane = tid & 31;
    const int nt_blk = blockIdx.x;
    const int m0t = blockIdx.y * 128;
    const int b   = blockIdx.z;

    __nv_bfloat16* Ah = (__nv_bfloat16*)(sm + OFF_AH);
    __nv_bfloat16* Al = (__nv_bfloat16*)(sm + OFF_AL);
    __nv_bfloat16* Bh = (__nv_bfloat16*)(sm + OFF_BH);
    __nv_bfloat16* Bl = (__nv_bfloat16*)(sm + OFF_BL);

    // ---- stage A: 128 rows x 128 k fp32 -> bf16 hi/lo (padded rows) ----
    #pragma unroll
    for (int i = 0; i < 16; i++){
        int idx = tid + i * 256;
        int row = idx >> 5, c4 = idx & 31;
        float4 v = *(const float4*)(W + (size_t)(m0t + row) * 128 + c4 * 4);
        __nv_bfloat16 h0,l0,h1,l1,h2,l2,h3,l3;
        split_bf16(v.x,h0,l0); split_bf16(v.y,h1,l1);
        split_bf16(v.z,h2,l2); split_bf16(v.w,h3,l3);
        uint2 uh = make_uint2(pack_bf2(h0,h1), pack_bf2(h2,h3));
        uint2 ul = make_uint2(pack_bf2(l0,l1), pack_bf2(l2,l3));
        *(uint2*)(Ah + row * AS + c4 * 4) = uh;
        *(uint2*)(Al + row * AS + c4 * 4) = ul;
    }
    // ---- stage B: flat 16K-bf16 tile copies into padded rows ----
    {
        size_t blob = ((size_t)(b * NTILE + nt_blk)) << 14;
        const uint4* sh = (const uint4*)(Bhi + blob);
        const uint4* sl = (const uint4*)(Blo + blob);
        #pragma unroll
        for (int i = 0; i < 8; i++){
            int idx = tid + i * 256;          // 2048 uint4
            int n = idx >> 4, kc = idx & 15;
            *(uint4*)(Bh + n * AS + kc * 8) = sh[idx];
            *(uint4*)(Bl + n * AS + kc * 8) = sl[idx];
        }
    }
    __syncthreads();

    // ---- fragment address precompute ----
    const int m0w = (wid >> 1) * 32;
    const int n0w = (wid & 1) * 64;
    const int row8 = lane & 7, quad = lane >> 3;
    const uint32_t sb = smem_u32(sm);

    uint32_t aoff[2], boff[2];
    #pragma unroll
    for (int mt = 0; mt < 2; mt++)
        aoff[mt] = sb + OFF_AH + 2 * ((m0w + mt*16 + ((quad & 1) << 3) + row8) * AS + ((quad >> 1) << 3));
    #pragma unroll
    for (int g = 0; g < 2; g++)
        boff[g] = sb + OFF_BH + 2 * ((n0w + g*32 + (quad << 3) + row8) * AS);

    float acc[2][8][4];
    #pragma unroll
    for (int mt = 0; mt < 2; mt++)
        #pragma unroll
        for (int nt = 0; nt < 8; nt++)
            #pragma unroll
            for (int q = 0; q < 4; q++) acc[mt][nt][q] = 0.f;

    // ---- mainloop: 8 k-steps of 16 ----
    #pragma unroll
    for (int ks = 0; ks < 8; ks++){
        const uint32_t kb = ks * 32;          // bytes (16 bf16)
        uint32_t ah[2][4], al[2][4], bh[2][2][4], bl[2][2][4];
        #pragma unroll
        for (int mt = 0; mt < 2; mt++){
            LDSM_X4(ah[mt][0], ah[mt][1], ah[mt][2], ah[mt][3], aoff[mt] + kb);
            LDSM_X4(al[mt][0], al[mt][1], al[mt][2], al[mt][3], aoff[mt] + kb + (OFF_AL - OFF_AH));
        }
        #pragma unroll
        for (int g = 0; g < 2; g++){
            LDSM_X4(bh[g][0][0], bh[g][0][1], bh[g][0][2], bh[g][0][3], boff[g] + kb);
            LDSM_X4(bh[g][1][0], bh[g][1][1], bh[g][1][2], bh[g][1][3], boff[g] + kb + 16);
            LDSM_X4(bl[g][0][0], bl[g][0][1], bl[g][0][2], bl[g][0][3], boff[g] + kb + (OFF_BL - OFF_BH));
            LDSM_X4(bl[g][1][0], bl[g][1][1], bl[g][1][2], bl[g][1][3], boff[g] + kb + (OFF_BL - OFF_BH) + 16);
        }
        #pragma unroll
        for (int mt = 0; mt < 2; mt++)
            #pragma unroll
            for (int nt = 0; nt < 8; nt++){
                int g = nt >> 2, j = nt & 3;
                MMA_BF16(acc[mt][nt], ah[mt], bh[g][0][j], bh[g][1][j]);   // Ahi*Bhi
                MMA_BF16(acc[mt][nt], ah[mt], bl[g][0][j], bl[g][1][j]);   // Ahi*Blo
                MMA_BF16(acc[mt][nt], al[mt], bh[g][0][j], bh[g][1][j]);   // Alo*Bhi
            }
    }

    // ---- epilogue ----
    const int n0t = nt_blk * 128;
    #pragma unroll
    for (int mt = 0; mt < 2; mt++){
        int r0 = m0w + mt*16 + (lane >> 2);
        float bv0 = bias[m0t + r0];
        float bv1 = bias[m0t + r0 + 8];
        #pragma unroll
        for (int nt = 0; nt < 8; nt++){
            int col = n0t + n0w + nt*8 + ((lane & 3) << 1);
            float d0 = acc[mt][nt][0] + bv0, d1 = acc[mt][nt][1] + bv0;
            float d2 = acc[mt][nt][2] + bv1, d3 = acc[mt][nt][3] + bv1;
            if (!remap){
                *(float2*)(Out + ((size_t)(b * Mtot + m0t + r0)     ) * HW + col) = make_float2(d0, d1);
                *(float2*)(Out + ((size_t)(b * Mtot + m0t + r0 + 8) ) * HW + col) = make_float2(d2, d3);
            } else {
                #pragma unroll
                for (int e = 0; e < 2; e++){
                    int p = col + e;
                    int y = p / 224, x = p - y * 224;
                    int w = (y / 7) * 32 + (x / 7);
                    int l = (y % 7) * 7 + (x % 7);
                    size_t o = ((size_t)(b * 384 + m0t + r0) * 1024 + w) * 49 + l;
                    Out[o]                    = e ? d1 : d0;
                    Out[o + (size_t)8 * HW]   = e ? d3 : d2;   // channel +8
                }
            }
        }
    }
}

// =====================================================================
// windowed attention: one CTA per (window, head). Input: window-major qkv.
// Output: bf16 hi/lo n-major tiles for the proj GEMM.
// =====================================================================
__global__ __launch_bounds__(256)
void attn_win(const float* __restrict__ qkv,
              __nv_bfloat16* __restrict__ Ahi,
              __nv_bfloat16* __restrict__ Alo)
{
    __shared__ __align__(16) float qs[16][52];
    __shared__ __align__(16) float ks[16][52];
    __shared__ __align__(16) float vT[52][16];
    __shared__ __align__(16) float ps[52][52];
    __shared__ __align__(16) float pT[52][52];

    const int tid = threadIdx.x;
    const int wi  = blockIdx.x;
    const int h   = blockIdx.y;
    const int b   = wi >> 10;
    const int w   = wi & 1023;
    const int wh  = w >> 5, ww = w & 31;
    const int prow = wh * 7, pcol = ww * 7;

    const float* qb = qkv + ((size_t)(b * 384 + h * 16)) * HW + (size_t)w * 49;
    const float* kb = qb + (size_t)128 * HW;
    const float* vb = qb + (size_t)256 * HW;

    // contiguous 49-float runs per channel
    for (int idx = tid; idx < 784; idx += 256){
        int c = idx / 49;
        int p = idx - c * 49;
        size_t off = (size_t)c * HW + p;
        qs[c][p] = qb[off] * 0.25f;   // 1/sqrt(16)
        ks[c][p] = kb[off];
        vT[p][c] = vb[off];
    }
    __syncthreads();

    // scores[l][m] = sum_c q[c][l]*k[c][m]
    if (tid < 169){
        int lt = (tid / 13) * 4;
        int mt = (tid % 13) * 4;
        float acc[4][4];
        #pragma unroll
        for (int i = 0; i < 4; i++)
            #pragma unroll
            for (int j = 0; j < 4; j++) acc[i][j] = 0.f;
        #pragma unroll 4
        for (int c = 0; c < 16; c++){
            float4 q4 = *(const float4*)&qs[c][lt];
            float4 k4 = *(const float4*)&ks[c][mt];
            float qv[4] = {q4.x, q4.y, q4.z, q4.w};
            float kv[4] = {k4.x, k4.y, k4.z, k4.w};
            #pragma unroll
            for (int i = 0; i < 4; i++)
                #pragma unroll
                for (int j = 0; j < 4; j++)
                    acc[i][j] += qv[i] * kv[j];
        }
        #pragma unroll
        for (int i = 0; i < 4; i++)
            #pragma unroll
            for (int j = 0; j < 4; j++)
                ps[lt + i][mt + j] = acc[i][j];
    }
    __syncthreads();

    // softmax over m -> transposed probs
    {
        int warp = tid >> 5, lane = tid & 31;
        for (int l = warp; l < 49; l += 8){
            float s0 = ps[l][lane];
            float s1 = (lane < 17) ? ps[l][lane + 32] : -3.4e38f;
            float mx = fmaxf(s0, s1);
            #pragma unroll
            for (int o = 16; o; o >>= 1) mx = fmaxf(mx, __shfl_xor_sync(0xffffffffu, mx, o));
            float e0 = __expf(s0 - mx);
            float e1 = (lane < 17) ? __expf(s1 - mx) : 0.f;
            float sm = e0 + e1;
            #pragma unroll
            for (int o = 16; o; o >>= 1) sm += __shfl_xor_sync(0xffffffffu, sm, o);
            float inv = 1.f / sm;
            pT[lane][l] = e0 * inv;
            if (lane < 17) pT[lane + 32][l] = e1 * inv;
        }
    }
    __syncthreads();

    // out[c][l] = sum_m vT[m][c]*pT[m][l]; direct hi/lo writeback to proj tiles
    if (tid < 196){
        int l  = tid >> 2;
        int c0 = (tid & 3) * 4;
        float a0 = 0.f, a1 = 0.f, a2 = 0.f, a3 = 0.f;
        for (int m = 0; m < 49; m++){
            float4 v4 = *(const float4*)&vT[m][c0];
            float pm = pT[m][l];
            a0 += v4.x * pm; a1 += v4.y * pm; a2 += v4.z * pm; a3 += v4.w * pm;
        }
        int y = prow + l / 7, x = pcol + l % 7;
        int p = y * 224 + x;
        int t = p >> 7, n = p & 127;
        size_t base = (((size_t)(b * NTILE + t)) * 128 + n) * 128 + h * 16 + c0;
        __nv_bfloat16 h0,l0,h1,l1,h2,l2,h3,l3;
        split_bf16(a0,h0,l0); split_bf16(a1,h1,l1);
        split_bf16(a2,h2,l2); split_bf16(a3,h3,l3);
        *(uint2*)(Ahi + base) = make_uint2(pack_bf2(h0,h1), pack_bf2(h2,h3));
        *(uint2*)(Alo + base) = make_uint2(pack_bf2(l0,l1), pack_bf2(l2,l3));
    }
}

// ---------------- launch ----------------
extern "C" void kernel_launch(void* const* d_in, const int* in_sizes, int n_in,
                              void* d_out, int out_size)
{
    const float* x     = (const float*)d_in[0];
    const float* w_qkv = (const float*)d_in[1];
    const float* b_qkv = (const float*)d_in[2];
    const float* w_out = (const float*)d_in[3];
    const float* b_out = (const float*)d_in[4];
    float* out = (float*)d_out;

    float *qkv = nullptr;
    __nv_bfloat16 *xhi, *xlo, *ahi, *alo;
    cudaGetSymbolAddress((void**)&qkv, g_qkv);
    cudaGetSymbolAddress((void**)&xhi, g_xhi);
    cudaGetSymbolAddress((void**)&xlo, g_xlo);
    cudaGetSymbolAddress((void**)&ahi, g_ahi);
    cudaGetSymbolAddress((void**)&alo, g_alo);

    cudaFuncSetAttribute(xconv,    cudaFuncAttributeMaxDynamicSharedMemorySize, XCONV_SMEM);
    cudaFuncSetAttribute(gemm_mma, cudaFuncAttributeMaxDynamicSharedMemorySize, GEMM_SMEM);

    xconv<<<BLOBS, 256, XCONV_SMEM>>>(x, xhi, xlo);
    gemm_mma<<<dim3(NTILE, 3, 4), 256, GEMM_SMEM>>>(w_qkv, xhi, xlo, b_qkv, qkv, 384, 1);
    attn_win<<<dim3(4096, 8), 256>>>(qkv, ahi, alo);
    gemm_mma<<<dim3(NTILE, 1, 4), 256, GEMM_SMEM>>>(w_out, ahi, alo, b_out, out, 128, 0);
}

// round 5
// speedup vs baseline: 1.5174x; 1.3021x over previous
#include <cuda_runtime.h>
#include <cuda_bf16.h>
#include <cstdint>

// ---------------- problem constants ----------------
#define HW    50176          // 224*224 (= 1024 windows * 49)
#define NTILE 392            // HW / 128

// scratch
__device__ float         g_qkv[77070336];   // [4][384][p' window-major] fp32
__device__ __nv_bfloat16 g_xhi[25690112];   // x tiles [4*392][n=128 (p')][k=128] bf16 hi
__device__ __nv_bfloat16 g_xlo[25690112];
__device__ __nv_bfloat16 g_ahi[25690112];   // attn-out tiles [4*392][n=128 (row-major pixel)][k=128]
__device__ __nv_bfloat16 g_alo[25690112];
__device__ __nv_bfloat16 g_whi[65536];      // w_qkv (384 rows) then w_out (128 rows), [row][128]
__device__ __nv_bfloat16 g_wlo[65536];

// ---------------- helpers ----------------
__device__ __forceinline__ uint32_t smem_u32(const void* p){
    uint32_t a;
    asm("{ .reg .u64 t; cvta.to.shared.u64 t, %1; cvt.u32.u64 %0, t; }" : "=r"(a) : "l"(p));
    return a;
}
__device__ __forceinline__ void split_bf16(float v, __nv_bfloat16& h, __nv_bfloat16& l){
    h = __float2bfloat16(v);
    l = __float2bfloat16(v - __bfloat162float(h));
}
__device__ __forceinline__ uint32_t pack_bf2(__nv_bfloat16 a, __nv_bfloat16 b){
    return (uint32_t)__bfloat16_as_ushort(a) | ((uint32_t)__bfloat16_as_ushort(b) << 16);
}

#define LDSM_X4(r0, r1, r2, r3, addr)                                                     \
    asm volatile("ldmatrix.sync.aligned.m8n8.x4.shared.b16 {%0,%1,%2,%3}, [%4];"          \
        : "=r"(r0), "=r"(r1), "=r"(r2), "=r"(r3) : "r"(addr))

#define MMA_BF16(d, a, b0, b1)                                                            \
    asm volatile("mma.sync.aligned.m16n8k16.row.col.f32.bf16.bf16.f32 "                   \
        "{%0,%1,%2,%3}, {%4,%5,%6,%7}, {%8,%9}, {%0,%1,%2,%3};"                           \
        : "+f"((d)[0]), "+f"((d)[1]), "+f"((d)[2]), "+f"((d)[3])                          \
        : "r"((a)[0]), "r"((a)[1]), "r"((a)[2]), "r"((a)[3]), "r"(b0), "r"(b1))

// =====================================================================
// weight fp32 -> bf16 hi/lo (one-shot, tiny)
// =====================================================================
__global__ void wconv(const float* __restrict__ W, __nv_bfloat16* __restrict__ Hi,
                      __nv_bfloat16* __restrict__ Lo, int n4)
{
    int i = blockIdx.x * 256 + threadIdx.x;
    if (i >= n4) return;
    float4 v = ((const float4*)W)[i];
    __nv_bfloat16 h0,l0,h1,l1,h2,l2,h3,l3;
    split_bf16(v.x,h0,l0); split_bf16(v.y,h1,l1);
    split_bf16(v.z,h2,l2); split_bf16(v.w,h3,l3);
    *(uint2*)(Hi + i*4) = make_uint2(pack_bf2(h0,h1), pack_bf2(h2,h3));
    *(uint2*)(Lo + i*4) = make_uint2(pack_bf2(l0,l1), pack_bf2(l2,l3));
}

// =====================================================================
// x -> window-major bf16 hi/lo tiles: tile[n][k], n = window-major pixel p'
// =====================================================================
#define XS 131
#define XCONV_SMEM (128*XS*4 + 512)
__global__ __launch_bounds__(256)
void xconv(const float* __restrict__ X, __nv_bfloat16* __restrict__ Hi, __nv_bfloat16* __restrict__ Lo)
{
    extern __shared__ char xsm[];
    float* ts  = (float*)xsm;                 // [k 128][XS] indexed by n
    int*   pix = (int*)(xsm + 128*XS*4);
    const int tid = threadIdx.x;
    const int bt = blockIdx.x;
    const int b = bt / NTILE, t = bt - b * NTILE;

    if (tid < 128){
        int n = t * 128 + tid;                // window-major pixel id
        int w = n / 49, l = n - w * 49;
        int y = (w >> 5) * 7 + l / 7;
        int x = (w & 31) * 7 + l % 7;
        pix[tid] = y * 224 + x;
    }
    __syncthreads();

    const float* xb = X + (size_t)b * 128 * HW;
    {
        int nl = tid & 127;
        int k0 = tid >> 7;
        int p  = pix[nl];
        #pragma unroll 8
        for (int i = 0; i < 64; i++){
            int k = k0 + i * 2;
            ts[k * XS + nl] = xb[(size_t)k * HW + p];
        }
    }
    __syncthreads();

    size_t ob = (size_t)bt << 14;
    #pragma unroll
    for (int i = 0; i < 8; i++){
        int idx = tid + i * 256;               // 2048 (n, kc) units
        int n = idx >> 4, kc = idx & 15;
        uint32_t rh[4], rl[4];
        #pragma unroll
        for (int j = 0; j < 4; j++){
            float v0 = ts[(kc*8 + 2*j    ) * XS + n];
            float v1 = ts[(kc*8 + 2*j + 1) * XS + n];
            __nv_bfloat16 h0, l0, h1, l1;
            split_bf16(v0, h0, l0); split_bf16(v1, h1, l1);
            rh[j] = pack_bf2(h0, h1);
            rl[j] = pack_bf2(l0, l1);
        }
        *(uint4*)(Hi + ob + n*128 + kc*8) = make_uint4(rh[0], rh[1], rh[2], rh[3]);
        *(uint4*)(Lo + ob + n*128 + kc*8) = make_uint4(rl[0], rl[1], rl[2], rl[3]);
    }
}

// =====================================================================
// mma.sync GEMM: Out[b][m][n] = sum_k W[m][k]*B[n][k] + bias[m]
// K = 2 chunks of 64, single-buffered smem (72KB) -> 2 CTAs/SM.
// 8 warps, warp tile 32x64, hi/lo 3-pass compensation.
// =====================================================================
#define CAS 72                     // row stride (bf16) per chunk: 64 data + 8 pad (144B, 16B-mult)
#define REG 18432                  // bytes per array (128 rows * 144B)
#define OFF_AL REG
#define OFF_BH (2*REG)
#define OFF_BL (3*REG)
#define GEMM_SMEM (4*REG)          // 73728

__global__ __launch_bounds__(256, 2)
void gemm_tc(const __nv_bfloat16* __restrict__ Whi, const __nv_bfloat16* __restrict__ Wlo, int wofs,
             const __nv_bfloat16* __restrict__ Bhi, const __nv_bfloat16* __restrict__ Blo,
             const float* __restrict__ bias, float* __restrict__ Out, int Mtot)
{
    extern __shared__ char sm[];
    const uint32_t sb = smem_u32(sm);
    const int tid  = threadIdx.x;
    const int wid  = tid >> 5;
    const int lane = tid & 31;
    const int nt_blk = blockIdx.x;
    const int m0t = blockIdx.y * 128;
    const int b   = blockIdx.z;

    const __nv_bfloat16* wh = Whi + wofs + (size_t)m0t * 128;
    const __nv_bfloat16* wl = Wlo + wofs + (size_t)m0t * 128;
    const size_t bb = ((size_t)(b * NTILE + nt_blk)) << 14;
    const __nv_bfloat16* bhp = Bhi + bb;
    const __nv_bfloat16* blp = Blo + bb;

    const int m0w = (wid >> 1) * 32;
    const int n0w = (wid & 1) * 64;
    const int row8 = lane & 7, quad = lane >> 3;

    uint32_t aoff[2], boff[2];
    #pragma unroll
    for (int mt = 0; mt < 2; mt++)
        aoff[mt] = sb + (uint32_t)((m0w + mt*16 + ((quad & 1) << 3) + row8) * 144 + ((quad >> 1) << 4));
    #pragma unroll
    for (int g = 0; g < 2; g++)
        boff[g] = sb + OFF_BH + (uint32_t)((n0w + g*32 + (quad << 3) + row8) * 144);

    float acc[2][8][4];
    #pragma unroll
    for (int mt = 0; mt < 2; mt++)
        #pragma unroll
        for (int nt = 0; nt < 8; nt++)
            #pragma unroll
            for (int q = 0; q < 4; q++) acc[mt][nt][q] = 0.f;

    // fixed per-thread copy coordinates: 2048 16B pieces per array pair
    const int c_hl    = tid >> 7;          // 0: hi, 1: lo (with i parity below)
    (void)c_hl;

    #pragma unroll
    for (int chunk = 0; chunk < 2; chunk++){
        if (chunk) __syncthreads();
        // ---- stage A (hi+lo): 2048 x 16B ----
        #pragma unroll
        for (int i = 0; i < 8; i++){
            int idx = tid + i * 256;           // 0..2047
            int hl = idx >> 10;                // 0..1
            int r  = idx & 1023;
            int row = r >> 3, piece = r & 7;   // row 0..127, piece 0..7 (8 bf16 each)
            const __nv_bfloat16* src = (hl ? wl : wh) + row * 128 + chunk * 64 + piece * 8;
            *(uint4*)(sm + hl * OFF_AL + row * 144 + piece * 16) = *(const uint4*)src;
        }
        // ---- stage B (hi+lo) ----
        #pragma unroll
        for (int i = 0; i < 8; i++){
            int idx = tid + i * 256;
            int hl = idx >> 10;
            int r  = idx & 1023;
            int row = r >> 3, piece = r & 7;
            const __nv_bfloat16* src = (hl ? blp : bhp) + row * 128 + chunk * 64 + piece * 8;
            *(uint4*)(sm + OFF_BH + hl * REG + row * 144 + piece * 16) = *(const uint4*)src;
        }
        __syncthreads();

        // ---- compute: 4 k-steps of 16 ----
        #pragma unroll
        for (int ks = 0; ks < 4; ks++){
            const uint32_t kb = ks * 32;       // bytes
            uint32_t ah[2][4], al[2][4], bh[2][2][4], bl[2][2][4];
            #pragma unroll
            for (int mt = 0; mt < 2; mt++){
                LDSM_X4(ah[mt][0], ah[mt][1], ah[mt][2], ah[mt][3], aoff[mt] + kb);
                LDSM_X4(al[mt][0], al[mt][1], al[mt][2], al[mt][3], aoff[mt] + kb + OFF_AL);
            }
            #pragma unroll
            for (int g = 0; g < 2; g++){
                LDSM_X4(bh[g][0][0], bh[g][0][1], bh[g][0][2], bh[g][0][3], boff[g] + kb);
                LDSM_X4(bh[g][1][0], bh[g][1][1], bh[g][1][2], bh[g][1][3], boff[g] + kb + 16);
                LDSM_X4(bl[g][0][0], bl[g][0][1], bl[g][0][2], bl[g][0][3], boff[g] + kb + REG);
                LDSM_X4(bl[g][1][0], bl[g][1][1], bl[g][1][2], bl[g][1][3], boff[g] + kb + REG + 16);
            }
            #pragma unroll
            for (int mt = 0; mt < 2; mt++)
                #pragma unroll
                for (int nt = 0; nt < 8; nt++){
                    int g = nt >> 2, j = nt & 3;
                    MMA_BF16(acc[mt][nt], ah[mt], bh[g][0][j], bh[g][1][j]);   // Ahi*Bhi
                    MMA_BF16(acc[mt][nt], ah[mt], bl[g][0][j], bl[g][1][j]);   // Ahi*Blo
                    MMA_BF16(acc[mt][nt], al[mt], bh[g][0][j], bh[g][1][j]);   // Alo*Bhi
                }
        }
    }

    // ---- epilogue: clean coalesced float2 stores ----
    const int n0t = nt_blk * 128;
    #pragma unroll
    for (int mt = 0; mt < 2; mt++){
        int r0 = m0w + mt*16 + (lane >> 2);
        float bv0 = bias[m0t + r0];
        float bv1 = bias[m0t + r0 + 8];
        #pragma unroll
        for (int nt = 0; nt < 8; nt++){
            int col = n0t + n0w + nt*8 + ((lane & 3) << 1);
            *(float2*)(Out + ((size_t)(b * Mtot + m0t + r0)    ) * HW + col) =
                make_float2(acc[mt][nt][0] + bv0, acc[mt][nt][1] + bv0);
            *(float2*)(Out + ((size_t)(b * Mtot + m0t + r0 + 8)) * HW + col) =
                make_float2(acc[mt][nt][2] + bv1, acc[mt][nt][3] + bv1);
        }
    }
}

// =====================================================================
// windowed attention: one CTA (224 thr) per (window, head).
// Input: window-major qkv (contiguous 49-runs). Output: row-major-pixel bf16 tiles.
// =====================================================================
__global__ __launch_bounds__(224)
void attn_win(const float* __restrict__ qkv,
              __nv_bfloat16* __restrict__ Ahi,
              __nv_bfloat16* __restrict__ Alo)
{
    __shared__ __align__(16) float qs[16][52];
    __shared__ __align__(16) float ks[16][52];
    __shared__ __align__(16) float vT[52][16];
    __shared__ __align__(16) float ps[52][52];
    __shared__ __align__(16) float pT[52][52];

    const int tid = threadIdx.x;
    const int wi  = blockIdx.x;
    const int h   = blockIdx.y;
    const int b   = wi >> 10;
    const int w   = wi & 1023;
    const int prow = (w >> 5) * 7, pcol = (w & 31) * 7;

    const float* qb = qkv + ((size_t)(b * 384 + h * 16)) * HW + (size_t)w * 49;
    const float* kb = qb + (size_t)128 * HW;
    const float* vb = qb + (size_t)256 * HW;

    for (int idx = tid; idx < 784; idx += 224){
        int c = idx / 49;
        int p = idx - c * 49;
        size_t off = (size_t)c * HW + p;
        qs[c][p] = qb[off] * 0.25f;   // 1/sqrt(16)
        ks[c][p] = kb[off];
        vT[p][c] = vb[off];
    }
    __syncthreads();

    // scores[l][m] = sum_c q[c][l]*k[c][m]
    if (tid < 169){
        int lt = (tid / 13) * 4;
        int mt = (tid % 13) * 4;
        float acc[4][4];
        #pragma unroll
        for (int i = 0; i < 4; i++)
            #pragma unroll
            for (int j = 0; j < 4; j++) acc[i][j] = 0.f;
        #pragma unroll 4
        for (int c = 0; c < 16; c++){
            float4 q4 = *(const float4*)&qs[c][lt];
            float4 k4 = *(const float4*)&ks[c][mt];
            float qv[4] = {q4.x, q4.y, q4.z, q4.w};
            float kv[4] = {k4.x, k4.y, k4.z, k4.w};
            #pragma unroll
            for (int i = 0; i < 4; i++)
                #pragma unroll
                for (int j = 0; j < 4; j++)
                    acc[i][j] += qv[i] * kv[j];
        }
        #pragma unroll
        for (int i = 0; i < 4; i++)
            #pragma unroll
            for (int j = 0; j < 4; j++)
                ps[lt + i][mt + j] = acc[i][j];
    }
    __syncthreads();

    // softmax over m -> transposed probs (7 warps x 7 rows each)
    {
        int warp = tid >> 5, lane = tid & 31;
        for (int l = warp; l < 49; l += 7){
            float s0 = ps[l][lane];
            float s1 = (lane < 17) ? ps[l][lane + 32] : -3.4e38f;
            float mx = fmaxf(s0, s1);
            #pragma unroll
            for (int o = 16; o; o >>= 1) mx = fmaxf(mx, __shfl_xor_sync(0xffffffffu, mx, o));
            float e0 = __expf(s0 - mx);
            float e1 = (lane < 17) ? __expf(s1 - mx) : 0.f;
            float sm = e0 + e1;
            #pragma unroll
            for (int o = 16; o; o >>= 1) sm += __shfl_xor_sync(0xffffffffu, sm, o);
            float inv = 1.f / sm;
            pT[lane][l] = e0 * inv;
            if (lane < 17) pT[lane + 32][l] = e1 * inv;
        }
    }
    __syncthreads();

    // out[c][l] = sum_m vT[m][c]*pT[m][l]; direct hi/lo writeback (row-major pixel tiles)
    if (tid < 196){
        int l  = tid >> 2;
        int c0 = (tid & 3) * 4;
        float a0 = 0.f, a1 = 0.f, a2 = 0.f, a3 = 0.f;
        #pragma unroll 7
        for (int m = 0; m < 49; m++){
            float4 v4 = *(const float4*)&vT[m][c0];
            float pm = pT[m][l];
            a0 += v4.x * pm; a1 += v4.y * pm; a2 += v4.z * pm; a3 += v4.w * pm;
        }
        int y = prow + l / 7, x = pcol + l % 7;
        int p = y * 224 + x;
        int t = p >> 7, n = p & 127;
        size_t base = (((size_t)(b * NTILE + t)) * 128 + n) * 128 + h * 16 + c0;
        __nv_bfloat16 h0,l0,h1,l1,h2,l2,h3,l3;
        split_bf16(a0,h0,l0); split_bf16(a1,h1,l1);
        split_bf16(a2,h2,l2); split_bf16(a3,h3,l3);
        *(uint2*)(Ahi + base) = make_uint2(pack_bf2(h0,h1), pack_bf2(h2,h3));
        *(uint2*)(Alo + base) = make_uint2(pack_bf2(l0,l1), pack_bf2(l2,l3));
    }
}

// ---------------- launch ----------------
extern "C" void kernel_launch(void* const* d_in, const int* in_sizes, int n_in,
                              void* d_out, int out_size)
{
    const float* x     = (const float*)d_in[0];
    const float* w_qkv = (const float*)d_in[1];
    const float* b_qkv = (const float*)d_in[2];
    const float* w_out = (const float*)d_in[3];
    const float* b_out = (const float*)d_in[4];
    float* out = (float*)d_out;

    float *qkv = nullptr;
    __nv_bfloat16 *xhi, *xlo, *ahi, *alo, *whi, *wlo;
    cudaGetSymbolAddress((void**)&qkv, g_qkv);
    cudaGetSymbolAddress((void**)&xhi, g_xhi);
    cudaGetSymbolAddress((void**)&xlo, g_xlo);
    cudaGetSymbolAddress((void**)&ahi, g_ahi);
    cudaGetSymbolAddress((void**)&alo, g_alo);
    cudaGetSymbolAddress((void**)&whi, g_whi);
    cudaGetSymbolAddress((void**)&wlo, g_wlo);

    cudaFuncSetAttribute(xconv,   cudaFuncAttributeMaxDynamicSharedMemorySize, XCONV_SMEM);
    cudaFuncSetAttribute(gemm_tc, cudaFuncAttributeMaxDynamicSharedMemorySize, GEMM_SMEM);

    wconv<<<48, 256>>>(w_qkv, whi, wlo, 12288);                 // 384*128/4
    wconv<<<16, 256>>>(w_out, whi + 49152, wlo + 49152, 4096);  // 128*128/4
    xconv<<<4 * NTILE, 256, XCONV_SMEM>>>(x, xhi, xlo);
    gemm_tc<<<dim3(NTILE, 3, 4), 256, GEMM_SMEM>>>(whi, wlo, 0,     xhi, xlo, b_qkv, qkv, 384);
    attn_win<<<dim3(4096, 8), 224>>>(qkv, ahi, alo);
    gemm_tc<<<dim3(NTILE, 1, 4), 256, GEMM_SMEM>>>(whi, wlo, 49152, ahi, alo, b_out, out, 128);
}

// round 6
// speedup vs baseline: 1.9396x; 1.2782x over previous
#include <cuda_runtime.h>
#include <cuda_fp16.h>
#include <cstdint>

// ---------------- problem constants ----------------
#define HW    50176          // 224*224 (= 1024 windows * 49)
#define NTILE 392            // HW / 128

// scratch
__device__ float  g_qkv[77070336];   // [4][384][p' window-major] fp32
__device__ __half g_xh[25690112];    // x tiles [4*392][n=128 (p')][k=128] fp16
__device__ __half g_ah[25690112];    // attn-out tiles [4*392][n=128 (row-major pixel)][k=128]
__device__ __half g_wh[65536];       // w_qkv (384 rows) then w_out (128 rows), [row][128]

// ---------------- helpers ----------------
__device__ __forceinline__ uint32_t smem_u32(const void* p){
    uint32_t a;
    asm("{ .reg .u64 t; cvta.to.shared.u64 t, %1; cvt.u32.u64 %0, t; }" : "=r"(a) : "l"(p));
    return a;
}
__device__ __forceinline__ uint32_t pack_h2(float a, float b){
    __half2 h = __floats2half2_rn(a, b);
    return *(uint32_t*)&h;
}

#define LDSM_X4(r0, r1, r2, r3, addr)                                                     \
    asm volatile("ldmatrix.sync.aligned.m8n8.x4.shared.b16 {%0,%1,%2,%3}, [%4];"          \
        : "=r"(r0), "=r"(r1), "=r"(r2), "=r"(r3) : "r"(addr))

#define MMA_F16(d, a, b0, b1)                                                             \
    asm volatile("mma.sync.aligned.m16n8k16.row.col.f32.f16.f16.f32 "                     \
        "{%0,%1,%2,%3}, {%4,%5,%6,%7}, {%8,%9}, {%0,%1,%2,%3};"                           \
        : "+f"((d)[0]), "+f"((d)[1]), "+f"((d)[2]), "+f"((d)[3])                          \
        : "r"((a)[0]), "r"((a)[1]), "r"((a)[2]), "r"((a)[3]), "r"(b0), "r"(b1))

// =====================================================================
// weight fp32 -> fp16 (one-shot, tiny)
// =====================================================================
__global__ void wconv(const float* __restrict__ W, __half* __restrict__ Wh, int n4)
{
    int i = blockIdx.x * 256 + threadIdx.x;
    if (i >= n4) return;
    float4 v = ((const float4*)W)[i];
    *(uint2*)(Wh + i*4) = make_uint2(pack_h2(v.x, v.y), pack_h2(v.z, v.w));
}

// =====================================================================
// x -> window-major fp16 tiles: tile[n][k], n = window-major pixel p'
// =====================================================================
#define XS 131
#define XCONV_SMEM (128*XS*4 + 512)
__global__ __launch_bounds__(256)
void xconv(const float* __restrict__ X, __half* __restrict__ Xh)
{
    extern __shared__ char xsm[];
    float* ts  = (float*)xsm;                 // [k 128][XS] indexed by n
    int*   pix = (int*)(xsm + 128*XS*4);
    const int tid = threadIdx.x;
    const int bt = blockIdx.x;
    const int b = bt / NTILE, t = bt - b * NTILE;

    if (tid < 128){
        int n = t * 128 + tid;                // window-major pixel id
        int w = n / 49, l = n - w * 49;
        int y = (w >> 5) * 7 + l / 7;
        int x = (w & 31) * 7 + l % 7;
        pix[tid] = y * 224 + x;
    }
    __syncthreads();

    const float* xb = X + (size_t)b * 128 * HW;
    {
        int nl = tid & 127;
        int k0 = tid >> 7;
        int p  = pix[nl];
        #pragma unroll 8
        for (int i = 0; i < 64; i++){
            int k = k0 + i * 2;
            ts[k * XS + nl] = xb[(size_t)k * HW + p];
        }
    }
    __syncthreads();

    size_t ob = (size_t)bt << 14;             // 16384 fp16 per tile
    #pragma unroll
    for (int i = 0; i < 8; i++){
        int idx = tid + i * 256;              // 2048 (n, kc) units
        int n = idx >> 4, kc = idx & 15;
        uint32_t r[4];
        #pragma unroll
        for (int j = 0; j < 4; j++){
            float v0 = ts[(kc*8 + 2*j    ) * XS + n];
            float v1 = ts[(kc*8 + 2*j + 1) * XS + n];
            r[j] = pack_h2(v0, v1);
        }
        *(uint4*)(Xh + ob + n*128 + kc*8) = make_uint4(r[0], r[1], r[2], r[3]);
    }
}

// =====================================================================
// fp16 mma.sync GEMM: Out[b][m][n] = sum_k W[m][k]*B[n][k] + bias[m]
// CTA tile 128x128, whole K=128 staged (68KB smem). 8 warps, warp tile 32x64.
// =====================================================================
#define ASTRIDE 272                // 128 fp16 = 256B + 16B pad (272 mod 128 = 16 -> conflict-free)
#define OFF_B   (128*ASTRIDE)      // 34816
#define GEMM_SMEM (2*128*ASTRIDE)  // 69632

__global__ __launch_bounds__(256, 2)
void gemm_tc(const __half* __restrict__ Wh, int wofs,
             const __half* __restrict__ Bt,
             const float* __restrict__ bias, float* __restrict__ Out, int Mtot)
{
    extern __shared__ char sm[];
    const uint32_t sb = smem_u32(sm);
    const int tid  = threadIdx.x;
    const int wid  = tid >> 5;
    const int lane = tid & 31;
    const int nt_blk = blockIdx.x;
    const int m0t = blockIdx.y * 128;
    const int b   = blockIdx.z;

    const __half* wp = Wh + wofs + (size_t)m0t * 128;
    const __half* bp = Bt + (((size_t)(b * NTILE + nt_blk)) << 14);

    // ---- stage A and B: 2048 x 16B each, coalesced ----
    #pragma unroll
    for (int i = 0; i < 8; i++){
        int idx = tid + i * 256;               // 0..2047
        int row = idx >> 4, piece = idx & 15;
        *(uint4*)(sm + row * ASTRIDE + piece * 16) = *(const uint4*)(wp + row * 128 + piece * 8);
    }
    #pragma unroll
    for (int i = 0; i < 8; i++){
        int idx = tid + i * 256;
        int row = idx >> 4, piece = idx & 15;
        *(uint4*)(sm + OFF_B + row * ASTRIDE + piece * 16) = *(const uint4*)(bp + idx * 8);
    }
    __syncthreads();

    const int m0w = (wid >> 1) * 32;
    const int n0w = (wid & 1) * 64;
    const int row8 = lane & 7, quad = lane >> 3;

    uint32_t aoff[2], boff[2];
    #pragma unroll
    for (int mt = 0; mt < 2; mt++)
        aoff[mt] = sb + (uint32_t)((m0w + mt*16 + ((quad & 1) << 3) + row8) * ASTRIDE + ((quad >> 1) << 4));
    #pragma unroll
    for (int g = 0; g < 2; g++)
        boff[g] = sb + OFF_B + (uint32_t)((n0w + g*32 + (quad << 3) + row8) * ASTRIDE);

    float acc[2][8][4];
    #pragma unroll
    for (int mt = 0; mt < 2; mt++)
        #pragma unroll
        for (int nt = 0; nt < 8; nt++)
            #pragma unroll
            for (int q = 0; q < 4; q++) acc[mt][nt][q] = 0.f;

    // ---- mainloop: 8 k-steps of 16 ----
    #pragma unroll
    for (int ks = 0; ks < 8; ks++){
        const uint32_t kb = ks * 32;           // bytes (16 fp16)
        uint32_t af[2][4], bf[2][2][4];
        #pragma unroll
        for (int mt = 0; mt < 2; mt++)
            LDSM_X4(af[mt][0], af[mt][1], af[mt][2], af[mt][3], aoff[mt] + kb);
        #pragma unroll
        for (int g = 0; g < 2; g++){
            LDSM_X4(bf[g][0][0], bf[g][0][1], bf[g][0][2], bf[g][0][3], boff[g] + kb);
            LDSM_X4(bf[g][1][0], bf[g][1][1], bf[g][1][2], bf[g][1][3], boff[g] + kb + 16);
        }
        #pragma unroll
        for (int mt = 0; mt < 2; mt++)
            #pragma unroll
            for (int nt = 0; nt < 8; nt++){
                int g = nt >> 2, j = nt & 3;
                MMA_F16(acc[mt][nt], af[mt], bf[g][0][j], bf[g][1][j]);
            }
    }

    // ---- epilogue: clean coalesced float2 stores ----
    const int n0t = nt_blk * 128;
    #pragma unroll
    for (int mt = 0; mt < 2; mt++){
        int r0 = m0w + mt*16 + (lane >> 2);
        float bv0 = bias[m0t + r0];
        float bv1 = bias[m0t + r0 + 8];
        #pragma unroll
        for (int nt = 0; nt < 8; nt++){
            int col = n0t + n0w + nt*8 + ((lane & 3) << 1);
            *(float2*)(Out + ((size_t)(b * Mtot + m0t + r0)    ) * HW + col) =
                make_float2(acc[mt][nt][0] + bv0, acc[mt][nt][1] + bv0);
            *(float2*)(Out + ((size_t)(b * Mtot + m0t + r0 + 8)) * HW + col) =
                make_float2(acc[mt][nt][2] + bv1, acc[mt][nt][3] + bv1);
        }
    }
}

// =====================================================================
// windowed attention: one CTA (224 thr) per (window, head).
// Input: window-major qkv (contiguous 49-runs). Output: fp16 tiles (row-major pixel).
// =====================================================================
__global__ __launch_bounds__(224)
void attn_win(const float* __restrict__ qkv, __half* __restrict__ Ah)
{
    __shared__ __align__(16) float qs[16][52];
    __shared__ __align__(16) float ks[16][52];
    __shared__ __align__(16) float vT[52][16];
    __shared__ __align__(16) float ps[52][52];

    const int tid = threadIdx.x;
    const int wi  = blockIdx.x;
    const int h   = blockIdx.y;
    const int b   = wi >> 10;
    const int w   = wi & 1023;
    const int prow = (w >> 5) * 7, pcol = (w & 31) * 7;

    const float* qb = qkv + ((size_t)(b * 384 + h * 16)) * HW + (size_t)w * 49;
    const float* kb = qb + (size_t)128 * HW;
    const float* vb = qb + (size_t)256 * HW;

    // division-free coalesced loads: 196 threads, 4 channels each
    if (tid < 196){
        int c0 = tid / 49;                 // 0..3 (compile-time magic)
        int p  = tid - c0 * 49;
        #pragma unroll
        for (int j = 0; j < 4; j++){
            int c = c0 + j * 4;
            size_t off = (size_t)c * HW + p;
            qs[c][p] = qb[off] * 0.25f;    // 1/sqrt(16)
            ks[c][p] = kb[off];
            vT[p][c] = vb[off];
        }
    }
    __syncthreads();

    // scores[l][m] = sum_c q[c][l]*k[c][m] ; 13x13 tiles of 4x4
    if (tid < 169){
        int lt = (tid / 13) * 4;
        int mt = (tid % 13) * 4;
        float acc[4][4];
        #pragma unroll
        for (int i = 0; i < 4; i++)
            #pragma unroll
            for (int j = 0; j < 4; j++) acc[i][j] = 0.f;
        #pragma unroll 4
        for (int c = 0; c < 16; c++){
            float4 q4 = *(const float4*)&qs[c][lt];
            float4 k4 = *(const float4*)&ks[c][mt];
            float qv[4] = {q4.x, q4.y, q4.z, q4.w};
            float kv[4] = {k4.x, k4.y, k4.z, k4.w};
            #pragma unroll
            for (int i = 0; i < 4; i++)
                #pragma unroll
                for (int j = 0; j < 4; j++)
                    acc[i][j] += qv[i] * kv[j];
        }
        #pragma unroll
        for (int i = 0; i < 4; i++)
            #pragma unroll
            for (int j = 0; j < 4; j++)
                ps[lt + i][mt + j] = acc[i][j];
    }
    __syncthreads();

    // softmax over m, normalized IN PLACE (7 warps x 7 rows each)
    {
        int warp = tid >> 5, lane = tid & 31;
        for (int l = warp; l < 49; l += 7){
            float s0 = ps[l][lane];
            float s1 = (lane < 17) ? ps[l][lane + 32] : -3.4e38f;
            float mx = fmaxf(s0, s1);
            #pragma unroll
            for (int o = 16; o; o >>= 1) mx = fmaxf(mx, __shfl_xor_sync(0xffffffffu, mx, o));
            float e0 = __expf(s0 - mx);
            float e1 = (lane < 17) ? __expf(s1 - mx) : 0.f;
            float sm = e0 + e1;
            #pragma unroll
            for (int o = 16; o; o >>= 1) sm += __shfl_xor_sync(0xffffffffu, sm, o);
            float inv = 1.f / sm;
            ps[l][lane] = e0 * inv;
            if (lane < 17) ps[l][lane + 32] = e1 * inv;
        }
    }
    __syncthreads();

    // out[c][l] = sum_m vT[m][c]*ps[l][m]; direct fp16 writeback (row-major pixel tiles)
    if (tid < 196){
        int l  = tid >> 2;
        int c0 = (tid & 3) * 4;
        float a0 = 0.f, a1 = 0.f, a2 = 0.f, a3 = 0.f;
        #pragma unroll 7
        for (int m = 0; m < 49; m++){
            float4 v4 = *(const float4*)&vT[m][c0];
            float pm = ps[l][m];
            a0 += v4.x * pm; a1 += v4.y * pm; a2 += v4.z * pm; a3 += v4.w * pm;
        }
        int y = prow + l / 7, x = pcol + l % 7;
        int p = y * 224 + x;
        int t = p >> 7, n = p & 127;
        size_t base = (((size_t)(b * NTILE + t)) * 128 + n) * 128 + h * 16 + c0;
        *(uint2*)(Ah + base) = make_uint2(pack_h2(a0, a1), pack_h2(a2, a3));
    }
}

// ---------------- launch ----------------
extern "C" void kernel_launch(void* const* d_in, const int* in_sizes, int n_in,
                              void* d_out, int out_size)
{
    const float* x     = (const float*)d_in[0];
    const float* w_qkv = (const float*)d_in[1];
    const float* b_qkv = (const float*)d_in[2];
    const float* w_out = (const float*)d_in[3];
    const float* b_out = (const float*)d_in[4];
    float* out = (float*)d_out;

    float *qkv = nullptr;
    __half *xh, *ah, *wh;
    cudaGetSymbolAddress((void**)&qkv, g_qkv);
    cudaGetSymbolAddress((void**)&xh, g_xh);
    cudaGetSymbolAddress((void**)&ah, g_ah);
    cudaGetSymbolAddress((void**)&wh, g_wh);

    cudaFuncSetAttribute(xconv,   cudaFuncAttributeMaxDynamicSharedMemorySize, XCONV_SMEM);
    cudaFuncSetAttribute(gemm_tc, cudaFuncAttributeMaxDynamicSharedMemorySize, GEMM_SMEM);

    wconv<<<48, 256>>>(w_qkv, wh, 12288);              // 384*128/4
    wconv<<<16, 256>>>(w_out, wh + 49152, 4096);       // 128*128/4
    xconv<<<4 * NTILE, 256, XCONV_SMEM>>>(x, xh);
    gemm_tc<<<dim3(NTILE, 3, 4), 256, GEMM_SMEM>>>(wh, 0,     xh, b_qkv, qkv, 384);
    attn_win<<<dim3(4096, 8), 224>>>(qkv, ah);
    gemm_tc<<<dim3(NTILE, 1, 4), 256, GEMM_SMEM>>>(wh, 49152, ah, b_out, out, 128);
}

// round 7
// speedup vs baseline: 2.5991x; 1.3400x over previous
#include <cuda_runtime.h>
#include <cuda_fp16.h>
#include <cstdint>

// ---------------- problem constants ----------------
#define HW    50176          // 224*224 (= 1024 windows * 49)
#define NTILE 392            // HW / 128

// scratch
__device__ float  g_qkv[77070336];   // [4][384][p' window-major] fp32
__device__ __half g_xh[25690112];    // x tiles [4*392][n=128 (p')][k=128] fp16
__device__ __half g_ah[25690112];    // attn-out tiles [4*392][n=128 (row-major pixel)][k=128]
__device__ __half g_wh[65536];       // w_qkv (384 rows) then w_out (128 rows), [row][128]

// ---------------- helpers ----------------
__device__ __forceinline__ uint32_t smem_u32(const void* p){
    uint32_t a;
    asm("{ .reg .u64 t; cvta.to.shared.u64 t, %1; cvt.u32.u64 %0, t; }" : "=r"(a) : "l"(p));
    return a;
}
__device__ __forceinline__ uint32_t pack_h2(float a, float b){
    __half2 h = __floats2half2_rn(a, b);
    return *(uint32_t*)&h;
}

#define LDSM_X4(r0, r1, r2, r3, addr)                                                     \
    asm volatile("ldmatrix.sync.aligned.m8n8.x4.shared.b16 {%0,%1,%2,%3}, [%4];"          \
        : "=r"(r0), "=r"(r1), "=r"(r2), "=r"(r3) : "r"(addr))

#define LDSM_X4T(r0, r1, r2, r3, addr)                                                    \
    asm volatile("ldmatrix.sync.aligned.m8n8.x4.trans.shared.b16 {%0,%1,%2,%3}, [%4];"    \
        : "=r"(r0), "=r"(r1), "=r"(r2), "=r"(r3) : "r"(addr))

#define MMA_F16(d, a, b0, b1)                                                             \
    asm volatile("mma.sync.aligned.m16n8k16.row.col.f32.f16.f16.f32 "                     \
        "{%0,%1,%2,%3}, {%4,%5,%6,%7}, {%8,%9}, {%0,%1,%2,%3};"                           \
        : "+f"((d)[0]), "+f"((d)[1]), "+f"((d)[2]), "+f"((d)[3])                          \
        : "r"((a)[0]), "r"((a)[1]), "r"((a)[2]), "r"((a)[3]), "r"(b0), "r"(b1))

// =====================================================================
// weight fp32 -> fp16 (one-shot, tiny)
// =====================================================================
__global__ void wconv(const float* __restrict__ W, __half* __restrict__ Wh, int n4)
{
    int i = blockIdx.x * 256 + threadIdx.x;
    if (i >= n4) return;
    float4 v = ((const float4*)W)[i];
    *(uint2*)(Wh + i*4) = make_uint2(pack_h2(v.x, v.y), pack_h2(v.z, v.w));
}

// =====================================================================
// x -> window-major fp16 tiles: tile[n][k], n = window-major pixel p'
// =====================================================================
#define XS 131
#define XCONV_SMEM (128*XS*4 + 512)
__global__ __launch_bounds__(256)
void xconv(const float* __restrict__ X, __half* __restrict__ Xh)
{
    extern __shared__ char xsm[];
    float* ts  = (float*)xsm;                 // [k 128][XS] indexed by n
    int*   pix = (int*)(xsm + 128*XS*4);
    const int tid = threadIdx.x;
    const int bt = blockIdx.x;
    const int b = bt / NTILE, t = bt - b * NTILE;

    if (tid < 128){
        int n = t * 128 + tid;                // window-major pixel id
        int w = n / 49, l = n - w * 49;
        int y = (w >> 5) * 7 + l / 7;
        int x = (w & 31) * 7 + l % 7;
        pix[tid] = y * 224 + x;
    }
    __syncthreads();

    const float* xb = X + (size_t)b * 128 * HW;
    {
        int nl = tid & 127;
        int k0 = tid >> 7;
        int p  = pix[nl];
        #pragma unroll 8
        for (int i = 0; i < 64; i++){
            int k = k0 + i * 2;
            ts[k * XS + nl] = xb[(size_t)k * HW + p];
        }
    }
    __syncthreads();

    size_t ob = (size_t)bt << 14;             // 16384 fp16 per tile
    #pragma unroll
    for (int i = 0; i < 8; i++){
        int idx = tid + i * 256;              // 2048 (n, kc) units
        int n = idx >> 4, kc = idx & 15;
        uint32_t r[4];
        #pragma unroll
        for (int j = 0; j < 4; j++){
            float v0 = ts[(kc*8 + 2*j    ) * XS + n];
            float v1 = ts[(kc*8 + 2*j + 1) * XS + n];
            r[j] = pack_h2(v0, v1);
        }
        *(uint4*)(Xh + ob + n*128 + kc*8) = make_uint4(r[0], r[1], r[2], r[3]);
    }
}

// =====================================================================
// fp16 mma.sync GEMM: Out[b][m][n] = sum_k W[m][k]*B[n][k] + bias[m]
// CTA tile 128x128, whole K=128 staged (68KB smem). 8 warps, warp tile 32x64.
// =====================================================================
#define ASTRIDE 272                // 128 fp16 = 256B + 16B pad
#define OFF_B   (128*ASTRIDE)      // 34816
#define GEMM_SMEM (2*128*ASTRIDE)  // 69632

__global__ __launch_bounds__(256, 2)
void gemm_tc(const __half* __restrict__ Wh, int wofs,
             const __half* __restrict__ Bt,
             const float* __restrict__ bias, float* __restrict__ Out, int Mtot)
{
    extern __shared__ char sm[];
    const uint32_t sb = smem_u32(sm);
    const int tid  = threadIdx.x;
    const int wid  = tid >> 5;
    const int lane = tid & 31;
    const int nt_blk = blockIdx.x;
    const int m0t = blockIdx.y * 128;
    const int b   = blockIdx.z;

    const __half* wp = Wh + wofs + (size_t)m0t * 128;
    const __half* bp = Bt + (((size_t)(b * NTILE + nt_blk)) << 14);

    #pragma unroll
    for (int i = 0; i < 8; i++){
        int idx = tid + i * 256;
        int row = idx >> 4, piece = idx & 15;
        *(uint4*)(sm + row * ASTRIDE + piece * 16) = *(const uint4*)(wp + row * 128 + piece * 8);
    }
    #pragma unroll
    for (int i = 0; i < 8; i++){
        int idx = tid + i * 256;
        int row = idx >> 4, piece = idx & 15;
        *(uint4*)(sm + OFF_B + row * ASTRIDE + piece * 16) = *(const uint4*)(bp + idx * 8);
    }
    __syncthreads();

    const int m0w = (wid >> 1) * 32;
    const int n0w = (wid & 1) * 64;
    const int row8 = lane & 7, quad = lane >> 3;

    uint32_t aoff[2], boff[2];
    #pragma unroll
    for (int mt = 0; mt < 2; mt++)
        aoff[mt] = sb + (uint32_t)((m0w + mt*16 + ((quad & 1) << 3) + row8) * ASTRIDE + ((quad >> 1) << 4));
    #pragma unroll
    for (int g = 0; g < 2; g++)
        boff[g] = sb + OFF_B + (uint32_t)((n0w + g*32 + (quad << 3) + row8) * ASTRIDE);

    float acc[2][8][4];
    #pragma unroll
    for (int mt = 0; mt < 2; mt++)
        #pragma unroll
        for (int nt = 0; nt < 8; nt++)
            #pragma unroll
            for (int q = 0; q < 4; q++) acc[mt][nt][q] = 0.f;

    #pragma unroll
    for (int ks = 0; ks < 8; ks++){
        const uint32_t kb = ks * 32;
        uint32_t af[2][4], bf[2][2][4];
        #pragma unroll
        for (int mt = 0; mt < 2; mt++)
            LDSM_X4(af[mt][0], af[mt][1], af[mt][2], af[mt][3], aoff[mt] + kb);
        #pragma unroll
        for (int g = 0; g < 2; g++){
            LDSM_X4(bf[g][0][0], bf[g][0][1], bf[g][0][2], bf[g][0][3], boff[g] + kb);
            LDSM_X4(bf[g][1][0], bf[g][1][1], bf[g][1][2], bf[g][1][3], boff[g] + kb + 16);
        }
        #pragma unroll
        for (int mt = 0; mt < 2; mt++)
            #pragma unroll
            for (int nt = 0; nt < 8; nt++){
                int g = nt >> 2, j = nt & 3;
                MMA_F16(acc[mt][nt], af[mt], bf[g][0][j], bf[g][1][j]);
            }
    }

    const int n0t = nt_blk * 128;
    #pragma unroll
    for (int mt = 0; mt < 2; mt++){
        int r0 = m0w + mt*16 + (lane >> 2);
        float bv0 = bias[m0t + r0];
        float bv1 = bias[m0t + r0 + 8];
        #pragma unroll
        for (int nt = 0; nt < 8; nt++){
            int col = n0t + n0w + nt*8 + ((lane & 3) << 1);
            *(float2*)(Out + ((size_t)(b * Mtot + m0t + r0)    ) * HW + col) =
                make_float2(acc[mt][nt][0] + bv0, acc[mt][nt][1] + bv0);
            *(float2*)(Out + ((size_t)(b * Mtot + m0t + r0 + 8)) * HW + col) =
                make_float2(acc[mt][nt][2] + bv1, acc[mt][nt][3] + bv1);
        }
    }
}

// =====================================================================
// tensor-core windowed attention: one CTA (128 thr / 4 warps) per (window, head)
// =====================================================================
__global__ __launch_bounds__(128)
void attn_mma(const float* __restrict__ qkv, __half* __restrict__ Ah)
{
    __shared__ __align__(16) __half qs[64*24];   // Q [pos][c], pitch 24 fp16 (48B); reused as out-stage
    __shared__ __align__(16) __half ks[64*24];   // K [pos][c]
    __shared__ __align__(16) __half vs[64*24];   // V [pos][c] (rows 49..63 zeroed)
    __shared__ __align__(16) float  Ssm[64*66];  // scores [l][m]
    __shared__ __align__(16) __half Psm[64*72];  // probs  [l][m] fp16, pitch 72

    const int tid  = threadIdx.x;
    const int lane = tid & 31;
    const int wrp  = tid >> 5;
    const int wi   = blockIdx.x;
    const int h    = blockIdx.y;
    const int b    = wi >> 10;
    const int w    = wi & 1023;
    const int prow = (w >> 5) * 7, pcol = (w & 31) * 7;

    const float* qb = qkv + ((size_t)(b * 384 + h * 16)) * HW + (size_t)w * 49;
    const float* kb = qb + (size_t)128 * HW;
    const float* vb = qb + (size_t)256 * HW;

    // ---- load q,k,v -> fp16 smem [pos][c] ----
    for (int idx = tid; idx < 784; idx += 128){
        int c = idx / 49;
        int p = idx - c * 49;
        size_t off = (size_t)c * HW + p;
        qs[p*24 + c] = __float2half(qb[off] * 0.25f);   // 1/sqrt(16)
        ks[p*24 + c] = __float2half(kb[off]);
        vs[p*24 + c] = __float2half(vb[off]);
    }
    // zero V pad rows 49..63 (720B)
    if (tid < 90) ((uint2*)(vs + 49*24))[tid] = make_uint2(0u, 0u);
    __syncthreads();

    const uint32_t qsb = smem_u32(qs), ksb = smem_u32(ks), vsb = smem_u32(vs), Pb = smem_u32(Psm);
    const int row8 = lane & 7, quad = lane >> 3;

    // ---- gemm1: S[l][m] = Q[l][:] . K[m][:]  (warp = 16 l-rows, m = 0..63) ----
    {
        uint32_t af[4];
        LDSM_X4(af[0], af[1], af[2], af[3],
                qsb + (uint32_t)((16*wrp + ((quad & 1) << 3) + row8) * 48 + ((quad >> 1) << 4)));
        float sc[8][4];
        #pragma unroll
        for (int g = 0; g < 2; g++){
            uint32_t b0[4], b1[4];
            uint32_t ba = ksb + (uint32_t)((g*32 + quad*8 + row8) * 48);
            LDSM_X4(b0[0], b0[1], b0[2], b0[3], ba);
            LDSM_X4(b1[0], b1[1], b1[2], b1[3], ba + 16);
            #pragma unroll
            for (int j = 0; j < 4; j++){
                int nt = g*4 + j;
                sc[nt][0] = sc[nt][1] = sc[nt][2] = sc[nt][3] = 0.f;
                MMA_F16(sc[nt], af, b0[j], b1[j]);
            }
        }
        int l0 = 16*wrp + (lane >> 2);
        int m0 = 2*(lane & 3);
        #pragma unroll
        for (int nt = 0; nt < 8; nt++){
            *(float2*)&Ssm[ l0      * 66 + nt*8 + m0] = make_float2(sc[nt][0], sc[nt][1]);
            *(float2*)&Ssm[(l0 + 8) * 66 + nt*8 + m0] = make_float2(sc[nt][2], sc[nt][3]);
        }
    }
    __syncthreads();

    // ---- softmax: 2 lanes per row; all 128 threads participate (rows>48 clamp/dup) ----
    {
        int l = tid >> 1; if (l > 48) l = 48;
        int half = tid & 1;
        int m0 = half * 25;
        int cnt = 25 - half;                 // 25 or 24
        float e[25];
        float mx = -1e30f;
        #pragma unroll
        for (int j = 0; j < 25; j++){
            float s = (j < cnt) ? Ssm[l*66 + m0 + j] : -1e30f;
            e[j] = s;
            mx = fmaxf(mx, s);
        }
        mx = fmaxf(mx, __shfl_xor_sync(0xffffffffu, mx, 1));
        float sum = 0.f;
        #pragma unroll
        for (int j = 0; j < 25; j++){
            float v = __expf(e[j] - mx);
            v = (j < cnt) ? v : 0.f;
            e[j] = v;
            sum += v;
        }
        sum += __shfl_xor_sync(0xffffffffu, sum, 1);
        float inv = 1.f / sum;
        #pragma unroll
        for (int j = 0; j < 25; j++)
            if (j < cnt) Psm[l*72 + m0 + j] = __float2half(e[j] * inv);
        if (half){
            #pragma unroll
            for (int m = 49; m < 64; m++) Psm[l*72 + m] = __float2half(0.f);
        }
    }
    __syncthreads();

    // ---- gemm2: out[l][c] = sum_m P[l][m] * V[m][c] ----
    {
        float oc[2][4];
        #pragma unroll
        for (int n = 0; n < 2; n++)
            #pragma unroll
            for (int q = 0; q < 4; q++) oc[n][q] = 0.f;

        #pragma unroll
        for (int ksp = 0; ksp < 4; ksp++){
            uint32_t pf[4], vf[4];
            LDSM_X4(pf[0], pf[1], pf[2], pf[3],
                    Pb + (uint32_t)((16*wrp + ((quad & 1) << 3) + row8) * 144 + ksp*32 + ((quad >> 1) << 4)));
            LDSM_X4T(vf[0], vf[1], vf[2], vf[3],
                     vsb + (uint32_t)((ksp*16 + (lane & 15)) * 48 + ((lane >> 4) << 4)));
            MMA_F16(oc[0], pf, vf[0], vf[1]);
            MMA_F16(oc[1], pf, vf[2], vf[3]);
        }

        // stage to smem (reuse qs): out[pos][c], pitch 16 fp16 (32B)
        __half* ost = qs;
        int pr = 16*wrp + (lane >> 2);
        int c0 = 2*(lane & 3);
        #pragma unroll
        for (int n = 0; n < 2; n++){
            if (pr < 49)
                *(uint32_t*)(ost + pr*16 + n*8 + c0)     = pack_h2(oc[n][0], oc[n][1]);
            if (pr + 8 < 49)
                *(uint32_t*)(ost + (pr+8)*16 + n*8 + c0) = pack_h2(oc[n][2], oc[n][3]);
        }
    }
    __syncthreads();

    // ---- final coalesced write: 32B per pixel ----
    if (tid < 98){
        int p  = tid >> 1;
        int hf = tid & 1;
        int pix = (prow + p / 7) * 224 + pcol + (p % 7);
        int t = pix >> 7, n = pix & 127;
        size_t base = (((size_t)(b * NTILE + t)) * 128 + n) * 128 + h * 16 + hf * 8;
        *(uint4*)(Ah + base) = *(const uint4*)(qs + p*16 + hf*8);
    }
}

// ---------------- launch ----------------
extern "C" void kernel_launch(void* const* d_in, const int* in_sizes, int n_in,
                              void* d_out, int out_size)
{
    const float* x     = (const float*)d_in[0];
    const float* w_qkv = (const float*)d_in[1];
    const float* b_qkv = (const float*)d_in[2];
    const float* w_out = (const float*)d_in[3];
    const float* b_out = (const float*)d_in[4];
    float* out = (float*)d_out;

    float *qkv = nullptr;
    __half *xh, *ah, *wh;
    cudaGetSymbolAddress((void**)&qkv, g_qkv);
    cudaGetSymbolAddress((void**)&xh, g_xh);
    cudaGetSymbolAddress((void**)&ah, g_ah);
    cudaGetSymbolAddress((void**)&wh, g_wh);

    cudaFuncSetAttribute(xconv,   cudaFuncAttributeMaxDynamicSharedMemorySize, XCONV_SMEM);
    cudaFuncSetAttribute(gemm_tc, cudaFuncAttributeMaxDynamicSharedMemorySize, GEMM_SMEM);

    wconv<<<48, 256>>>(w_qkv, wh, 12288);              // 384*128/4
    wconv<<<16, 256>>>(w_out, wh + 49152, 4096);       // 128*128/4
    xconv<<<4 * NTILE, 256, XCONV_SMEM>>>(x, xh);
    gemm_tc<<<dim3(NTILE, 3, 4), 256, GEMM_SMEM>>>(wh, 0,     xh, b_qkv, qkv, 384);
    attn_mma<<<dim3(4096, 8), 128>>>(qkv, ah);
    gemm_tc<<<dim3(NTILE, 1, 4), 256, GEMM_SMEM>>>(wh, 49152, ah, b_out, out, 128);
}

// round 8
// speedup vs baseline: 3.8300x; 1.4736x over previous
#include <cuda_runtime.h>
#include <cuda_fp16.h>
#include <cstdint>

// ---------------- problem constants ----------------
#define HW    50176          // 224*224 (= 1024 windows * 49)
#define NTILE 392            // HW / 128

// scratch
__device__ __half g_qkvh[77070336];  // [4][384][p' window-major] fp16
__device__ __half g_xh[25690112];    // x tiles [4*392][n=128 (p')][k=128] fp16
__device__ __half g_ah[25690112];    // attn-out tiles [4*392][n=128 (row-major pixel)][k=128]
__device__ __half g_wh[65536];       // w_qkv (384 rows) then w_out (128 rows), [row][128]

// ---------------- helpers ----------------
__device__ __forceinline__ uint32_t smem_u32(const void* p){
    uint32_t a;
    asm("{ .reg .u64 t; cvta.to.shared.u64 t, %1; cvt.u32.u64 %0, t; }" : "=r"(a) : "l"(p));
    return a;
}
__device__ __forceinline__ uint32_t pack_h2(float a, float b){
    __half2 h = __floats2half2_rn(a, b);
    return *(uint32_t*)&h;
}

#define LDSM_X4(r0, r1, r2, r3, addr)                                                     \
    asm volatile("ldmatrix.sync.aligned.m8n8.x4.shared.b16 {%0,%1,%2,%3}, [%4];"          \
        : "=r"(r0), "=r"(r1), "=r"(r2), "=r"(r3) : "r"(addr))

#define LDSM_X4T(r0, r1, r2, r3, addr)                                                    \
    asm volatile("ldmatrix.sync.aligned.m8n8.x4.trans.shared.b16 {%0,%1,%2,%3}, [%4];"    \
        : "=r"(r0), "=r"(r1), "=r"(r2), "=r"(r3) : "r"(addr))

#define MMA_F16(d, a, b0, b1)                                                             \
    asm volatile("mma.sync.aligned.m16n8k16.row.col.f32.f16.f16.f32 "                     \
        "{%0,%1,%2,%3}, {%4,%5,%6,%7}, {%8,%9}, {%0,%1,%2,%3};"                           \
        : "+f"((d)[0]), "+f"((d)[1]), "+f"((d)[2]), "+f"((d)[3])                          \
        : "r"((a)[0]), "r"((a)[1]), "r"((a)[2]), "r"((a)[3]), "r"(b0), "r"(b1))

// =====================================================================
// weight fp32 -> fp16 (one-shot, tiny)
// =====================================================================
__global__ void wconv(const float* __restrict__ W, __half* __restrict__ Wh, int n4)
{
    int i = blockIdx.x * 256 + threadIdx.x;
    if (i >= n4) return;
    float4 v = ((const float4*)W)[i];
    *(uint2*)(Wh + i*4) = make_uint2(pack_h2(v.x, v.y), pack_h2(v.z, v.w));
}

// =====================================================================
// x -> window-major fp16 tiles: tile[n][k], n = window-major pixel p'
// =====================================================================
#define XS 131
#define XCONV_SMEM (128*XS*4 + 512)
__global__ __launch_bounds__(256)
void xconv(const float* __restrict__ X, __half* __restrict__ Xh)
{
    extern __shared__ char xsm[];
    float* ts  = (float*)xsm;                 // [k 128][XS] indexed by n
    int*   pix = (int*)(xsm + 128*XS*4);
    const int tid = threadIdx.x;
    const int bt = blockIdx.x;
    const int b = bt / NTILE, t = bt - b * NTILE;

    if (tid < 128){
        int n = t * 128 + tid;                // window-major pixel id
        int w = n / 49, l = n - w * 49;
        int y = (w >> 5) * 7 + l / 7;
        int x = (w & 31) * 7 + l % 7;
        pix[tid] = y * 224 + x;
    }
    __syncthreads();

    const float* xb = X + (size_t)b * 128 * HW;
    {
        int nl = tid & 127;
        int k0 = tid >> 7;
        int p  = pix[nl];
        #pragma unroll 8
        for (int i = 0; i < 64; i++){
            int k = k0 + i * 2;
            ts[k * XS + nl] = xb[(size_t)k * HW + p];
        }
    }
    __syncthreads();

    size_t ob = (size_t)bt << 14;
    #pragma unroll
    for (int i = 0; i < 8; i++){
        int idx = tid + i * 256;
        int n = idx >> 4, kc = idx & 15;
        uint32_t r[4];
        #pragma unroll
        for (int j = 0; j < 4; j++){
            float v0 = ts[(kc*8 + 2*j    ) * XS + n];
            float v1 = ts[(kc*8 + 2*j + 1) * XS + n];
            r[j] = pack_h2(v0, v1);
        }
        *(uint4*)(Xh + ob + n*128 + kc*8) = make_uint4(r[0], r[1], r[2], r[3]);
    }
}

// =====================================================================
// fp16 mma.sync GEMM: Out[b][m][n] = sum_k W[m][k]*B[n][k] + bias[m]
// fp16out=1 -> __half output, else fp32.
// =====================================================================
#define ASTRIDE 272
#define OFF_B   (128*ASTRIDE)
#define GEMM_SMEM (2*128*ASTRIDE)  // 69632

__global__ __launch_bounds__(256, 2)
void gemm_tc(const __half* __restrict__ Wh, int wofs,
             const __half* __restrict__ Bt,
             const float* __restrict__ bias, void* __restrict__ OutV,
             int Mtot, int fp16out)
{
    extern __shared__ char sm[];
    const uint32_t sb = smem_u32(sm);
    const int tid  = threadIdx.x;
    const int wid  = tid >> 5;
    const int lane = tid & 31;
    const int nt_blk = blockIdx.x;
    const int m0t = blockIdx.y * 128;
    const int b   = blockIdx.z;

    const __half* wp = Wh + wofs + (size_t)m0t * 128;
    const __half* bp = Bt + (((size_t)(b * NTILE + nt_blk)) << 14);

    #pragma unroll
    for (int i = 0; i < 8; i++){
        int idx = tid + i * 256;
        int row = idx >> 4, piece = idx & 15;
        *(uint4*)(sm + row * ASTRIDE + piece * 16) = *(const uint4*)(wp + row * 128 + piece * 8);
    }
    #pragma unroll
    for (int i = 0; i < 8; i++){
        int idx = tid + i * 256;
        int row = idx >> 4, piece = idx & 15;
        *(uint4*)(sm + OFF_B + row * ASTRIDE + piece * 16) = *(const uint4*)(bp + idx * 8);
    }
    __syncthreads();

    const int m0w = (wid >> 1) * 32;
    const int n0w = (wid & 1) * 64;
    const int row8 = lane & 7, quad = lane >> 3;

    uint32_t aoff[2], boff[2];
    #pragma unroll
    for (int mt = 0; mt < 2; mt++)
        aoff[mt] = sb + (uint32_t)((m0w + mt*16 + ((quad & 1) << 3) + row8) * ASTRIDE + ((quad >> 1) << 4));
    #pragma unroll
    for (int g = 0; g < 2; g++)
        boff[g] = sb + OFF_B + (uint32_t)((n0w + g*32 + (quad << 3) + row8) * ASTRIDE);

    float acc[2][8][4];
    #pragma unroll
    for (int mt = 0; mt < 2; mt++)
        #pragma unroll
        for (int nt = 0; nt < 8; nt++)
            #pragma unroll
            for (int q = 0; q < 4; q++) acc[mt][nt][q] = 0.f;

    #pragma unroll
    for (int ks = 0; ks < 8; ks++){
        const uint32_t kb = ks * 32;
        uint32_t af[2][4], bf[2][2][4];
        #pragma unroll
        for (int mt = 0; mt < 2; mt++)
            LDSM_X4(af[mt][0], af[mt][1], af[mt][2], af[mt][3], aoff[mt] + kb);
        #pragma unroll
        for (int g = 0; g < 2; g++){
            LDSM_X4(bf[g][0][0], bf[g][0][1], bf[g][0][2], bf[g][0][3], boff[g] + kb);
            LDSM_X4(bf[g][1][0], bf[g][1][1], bf[g][1][2], bf[g][1][3], boff[g] + kb + 16);
        }
        #pragma unroll
        for (int mt = 0; mt < 2; mt++)
            #pragma unroll
            for (int nt = 0; nt < 8; nt++){
                int g = nt >> 2, j = nt & 3;
                MMA_F16(acc[mt][nt], af[mt], bf[g][0][j], bf[g][1][j]);
            }
    }

    const int n0t = nt_blk * 128;
    #pragma unroll
    for (int mt = 0; mt < 2; mt++){
        int r0 = m0w + mt*16 + (lane >> 2);
        float bv0 = bias[m0t + r0];
        float bv1 = bias[m0t + r0 + 8];
        #pragma unroll
        for (int nt = 0; nt < 8; nt++){
            int col = n0t + n0w + nt*8 + ((lane & 3) << 1);
            if (fp16out){
                __half* OutH = (__half*)OutV;
                *(uint32_t*)(OutH + ((size_t)(b * Mtot + m0t + r0)    ) * HW + col) =
                    pack_h2(acc[mt][nt][0] + bv0, acc[mt][nt][1] + bv0);
                *(uint32_t*)(OutH + ((size_t)(b * Mtot + m0t + r0 + 8)) * HW + col) =
                    pack_h2(acc[mt][nt][2] + bv1, acc[mt][nt][3] + bv1);
            } else {
                float* Out = (float*)OutV;
                *(float2*)(Out + ((size_t)(b * Mtot + m0t + r0)    ) * HW + col) =
                    make_float2(acc[mt][nt][0] + bv0, acc[mt][nt][1] + bv0);
                *(float2*)(Out + ((size_t)(b * Mtot + m0t + r0 + 8)) * HW + col) =
                    make_float2(acc[mt][nt][2] + bv1, acc[mt][nt][3] + bv1);
            }
        }
    }
}

// =====================================================================
// warp-per-head windowed attention: one CTA (256 thr) per window, warp = head.
// Register-resident softmax; C-frag == A-frag identity for P.
// =====================================================================
#define PH 136                     // smem pitch in halves (272B, conflict-free ldmatrix)
#define ATT_SMEM (3*64*PH*2)       // 52224

__global__ __launch_bounds__(256)
void attn_mma(const __half* __restrict__ qkv, __half* __restrict__ Ah)
{
    extern __shared__ __half asm_[];
    __half* qsm = asm_;                // [pos 64][128 c], pitch PH; reused as out-stage
    __half* ksm = asm_ + 64*PH;
    __half* vsm = asm_ + 128*PH;

    const int tid  = threadIdx.x;
    const int lane = tid & 31;
    const int wrp  = tid >> 5;         // head
    const int wi   = blockIdx.x;
    const int b    = wi >> 10;
    const int w    = wi & 1023;
    const int prow = (w >> 5) * 7, pcol = (w & 31) * 7;

    const __half* base = qkv + (size_t)b * 384 * HW + (size_t)w * 49;
    const __half hscale = __float2half(0.25f);   // 1/sqrt(16), exact

    // zero pad rows 49..63 of q/k/v (NaN-safety for masked lanes)
    if (tid < 255){
        ((uint4*)(qsm + 49*PH))[tid] = make_uint4(0,0,0,0);
        ((uint4*)(ksm + 49*PH))[tid] = make_uint4(0,0,0,0);
        ((uint4*)(vsm + 49*PH))[tid] = make_uint4(0,0,0,0);
    }
    // load q,k,v (128 c x 49 pos each)
    for (int idx = tid; idx < 6272; idx += 256){
        int c = idx / 49;
        int p = idx - c * 49;
        size_t off = (size_t)c * HW + p;
        qsm[p*PH + c] = __hmul(base[off], hscale);
        ksm[p*PH + c] = base[off + (size_t)128 * HW];
        vsm[p*PH + c] = base[off + (size_t)256 * HW];
    }
    __syncthreads();

    const uint32_t qsb = smem_u32(qsm), ksb = smem_u32(ksm), vsb = smem_u32(vsm);
    const int row8 = lane & 7, quad = lane >> 3;
    const int cbase = 2 * (lane & 3);
    const uint32_t hoff = (uint32_t)wrp * 32;    // head byte offset in a row

    // K fragments: 64 m-rows x 16 k (this head's channels), loaded once
    uint32_t kf[2][2][4];
    #pragma unroll
    for (int g = 0; g < 2; g++){
        uint32_t ba = ksb + (uint32_t)((g*32 + quad*8 + row8) * (PH*2)) + hoff;
        LDSM_X4(kf[g][0][0], kf[g][0][1], kf[g][0][2], kf[g][0][3], ba);
        LDSM_X4(kf[g][1][0], kf[g][1][1], kf[g][1][2], kf[g][1][3], ba + 16);
    }
    // V^T fragments: 4 ksteps x 16 c
    uint32_t vf[4][4];
    #pragma unroll
    for (int ksp = 0; ksp < 4; ksp++){
        uint32_t va = vsb + (uint32_t)((ksp*16 + (lane & 15)) * (PH*2)) + hoff + ((lane >> 4) << 4);
        LDSM_X4T(vf[ksp][0], vf[ksp][1], vf[ksp][2], vf[ksp][3], va);
    }

    __half* ost = qsm;   // out-stage: warp-private column slice [*, wrp*16 .. +16)

    #pragma unroll
    for (int lt = 0; lt < 4; lt++){
        const int l0 = lt * 16;
        uint32_t af[4];
        LDSM_X4(af[0], af[1], af[2], af[3],
                qsb + (uint32_t)((l0 + ((quad & 1) << 3) + row8) * (PH*2)) + hoff + ((quad >> 1) << 4));

        // S = Q . K^T  (16 rows x 64 cols, in registers)
        float sc[8][4];
        #pragma unroll
        for (int nt = 0; nt < 8; nt++){
            sc[nt][0] = sc[nt][1] = sc[nt][2] = sc[nt][3] = 0.f;
            int g = nt >> 2, j = nt & 3;
            MMA_F16(sc[nt], af, kf[g][0][j], kf[g][1][j]);
        }

        // mask cols >= 49, row max (rows r and r+8 separate)
        float mx0 = -1e30f, mx1 = -1e30f;
        #pragma unroll
        for (int nt = 0; nt < 8; nt++){
            int col0 = nt*8 + cbase;
            if (col0 > 48){ sc[nt][0] = -1e30f; sc[nt][2] = -1e30f; }
            if (col0 + 1 > 48){ sc[nt][1] = -1e30f; sc[nt][3] = -1e30f; }
            mx0 = fmaxf(mx0, fmaxf(sc[nt][0], sc[nt][1]));
            mx1 = fmaxf(mx1, fmaxf(sc[nt][2], sc[nt][3]));
        }
        mx0 = fmaxf(mx0, __shfl_xor_sync(0xffffffffu, mx0, 1));
        mx0 = fmaxf(mx0, __shfl_xor_sync(0xffffffffu, mx0, 2));
        mx1 = fmaxf(mx1, __shfl_xor_sync(0xffffffffu, mx1, 1));
        mx1 = fmaxf(mx1, __shfl_xor_sync(0xffffffffu, mx1, 2));

        float s0 = 0.f, s1 = 0.f;
        #pragma unroll
        for (int nt = 0; nt < 8; nt++){
            sc[nt][0] = __expf(sc[nt][0] - mx0);
            sc[nt][1] = __expf(sc[nt][1] - mx0);
            sc[nt][2] = __expf(sc[nt][2] - mx1);
            sc[nt][3] = __expf(sc[nt][3] - mx1);
            s0 += sc[nt][0] + sc[nt][1];
            s1 += sc[nt][2] + sc[nt][3];
        }
        s0 += __shfl_xor_sync(0xffffffffu, s0, 1);
        s0 += __shfl_xor_sync(0xffffffffu, s0, 2);
        s1 += __shfl_xor_sync(0xffffffffu, s1, 1);
        s1 += __shfl_xor_sync(0xffffffffu, s1, 2);
        float inv0 = 1.f / s0, inv1 = 1.f / s1;

        // O = P . V  (C-frag of S == A-frag of P)
        float oc[2][4];
        oc[0][0]=oc[0][1]=oc[0][2]=oc[0][3]=0.f;
        oc[1][0]=oc[1][1]=oc[1][2]=oc[1][3]=0.f;
        #pragma unroll
        for (int ksp = 0; ksp < 4; ksp++){
            uint32_t pf[4];
            pf[0] = pack_h2(sc[2*ksp  ][0]*inv0, sc[2*ksp  ][1]*inv0);
            pf[1] = pack_h2(sc[2*ksp  ][2]*inv1, sc[2*ksp  ][3]*inv1);
            pf[2] = pack_h2(sc[2*ksp+1][0]*inv0, sc[2*ksp+1][1]*inv0);
            pf[3] = pack_h2(sc[2*ksp+1][2]*inv1, sc[2*ksp+1][3]*inv1);
            MMA_F16(oc[0], pf, vf[ksp][0], vf[ksp][1]);
            MMA_F16(oc[1], pf, vf[ksp][2], vf[ksp][3]);
        }

        // stage O rows (warp-private cols)
        int pr = l0 + (lane >> 2);
        #pragma unroll
        for (int n = 0; n < 2; n++){
            if (pr < 49)
                *(uint32_t*)(ost + pr*PH + wrp*16 + n*8 + cbase) = pack_h2(oc[n][0], oc[n][1]);
            if (pr + 8 < 49)
                *(uint32_t*)(ost + (pr+8)*PH + wrp*16 + n*8 + cbase) = pack_h2(oc[n][2], oc[n][3]);
        }
    }
    __syncthreads();

    // coalesced writeback: 49 pos x 128 c = 784 uint4
    for (int idx = tid; idx < 784; idx += 256){
        int p = idx >> 4, ch = idx & 15;
        int pix = (prow + p / 7) * 224 + pcol + (p % 7);
        int t = pix >> 7, n = pix & 127;
        *(uint4*)(Ah + (((size_t)(b * NTILE + t)) * 128 + n) * 128 + ch*8) =
            *(const uint4*)(ost + p*PH + ch*8);
    }
}

// ---------------- launch ----------------
extern "C" void kernel_launch(void* const* d_in, const int* in_sizes, int n_in,
                              void* d_out, int out_size)
{
    const float* x     = (const float*)d_in[0];
    const float* w_qkv = (const float*)d_in[1];
    const float* b_qkv = (const float*)d_in[2];
    const float* w_out = (const float*)d_in[3];
    const float* b_out = (const float*)d_in[4];
    float* out = (float*)d_out;

    __half *qkvh, *xh, *ah, *wh;
    cudaGetSymbolAddress((void**)&qkvh, g_qkvh);
    cudaGetSymbolAddress((void**)&xh, g_xh);
    cudaGetSymbolAddress((void**)&ah, g_ah);
    cudaGetSymbolAddress((void**)&wh, g_wh);

    cudaFuncSetAttribute(xconv,    cudaFuncAttributeMaxDynamicSharedMemorySize, XCONV_SMEM);
    cudaFuncSetAttribute(gemm_tc,  cudaFuncAttributeMaxDynamicSharedMemorySize, GEMM_SMEM);
    cudaFuncSetAttribute(attn_mma, cudaFuncAttributeMaxDynamicSharedMemorySize, ATT_SMEM);

    wconv<<<48, 256>>>(w_qkv, wh, 12288);
    wconv<<<16, 256>>>(w_out, wh + 49152, 4096);
    xconv<<<4 * NTILE, 256, XCONV_SMEM>>>(x, xh);
    gemm_tc<<<dim3(NTILE, 3, 4), 256, GEMM_SMEM>>>(wh, 0,     xh, b_qkv, qkvh, 384, 1);
    attn_mma<<<4096, 256, ATT_SMEM>>>(qkvh, ah);
    gemm_tc<<<dim3(NTILE, 1, 4), 256, GEMM_SMEM>>>(wh, 49152, ah, b_out, out, 128, 0);
}